// round 11
// baseline (speedup 1.0000x reference)
#include <cuda_runtime.h>
#include <cstdint>
#include <math.h>

typedef unsigned long long u64;

#define BB 2
#define LL 256
#define HH 512
#define NHH 8
#define DHH 64

// ---------------- device scratch ----------------
__device__ float g_qt  [BB*NHH*LL*DHH];   // [b,n,l,d]
__device__ float g_kt  [BB*NHH*LL*DHH];   // [b,n,l,d]
__device__ float g_vt  [BB*NHH*LL*DHH];   // [b,n,l,d]
__device__ float g_w2  [BB*LL*NHH*HH];    // [b,q,n,h]
__device__ float g_ac  [BB*NHH*LL*LL];    // [b,n,q,k]
__device__ float g_attn[BB*NHH*LL*LL];    // [b,n,q,k]
__device__ float g_pre [BB*LL*HH];        // [b,q, n*64+d]

// ---------------- helpers ----------------
__device__ __forceinline__ u64 fma2(u64 a, u64 b, u64 c) {
    u64 d; asm("fma.rn.f32x2 %0, %1, %2, %3;" : "=l"(d) : "l"(a), "l"(b), "l"(c)); return d;
}
__device__ __forceinline__ u64 pack2(float x, float y) {
    u64 r; asm("mov.b64 %0, {%1, %2};" : "=l"(r) : "f"(x), "f"(y)); return r;
}
__device__ __forceinline__ float2 unpack2(u64 v) {
    float2 r; asm("mov.b64 {%0, %1}, %2;" : "=f"(r.x), "=f"(r.y) : "l"(v)); return r;
}
__device__ __forceinline__ uint32_t smem_u32(const void* p) {
    return (uint32_t)__cvta_generic_to_shared(p);
}

#define CP_ASYNC16(dst, src) asm volatile("cp.async.cg.shared.global [%0], [%1], 16;" :: "r"(dst), "l"(src))
#define CP_COMMIT()          asm volatile("cp.async.commit_group;")
#define CP_WAIT4()           asm volatile("cp.async.wait_group 4;")

// ---------------- shared 64x64 mma inner (32-k step) ----------------
__device__ __forceinline__ void mma32(const float (*As)[68], const float (*Bs)[68],
                                      int ty4, int tx4, u64 acc[2][4]) {
#pragma unroll
    for (int kk = 0; kk < 32; kk++) {
        ulonglong2 a2 = *(const ulonglong2*)&As[kk][ty4];
        float4 bv = *(const float4*)&Bs[kk][tx4];
        u64 b0 = pack2(bv.x, bv.x), b1 = pack2(bv.y, bv.y);
        u64 b2 = pack2(bv.z, bv.z), b3 = pack2(bv.w, bv.w);
        acc[0][0] = fma2(a2.x, b0, acc[0][0]); acc[1][0] = fma2(a2.y, b0, acc[1][0]);
        acc[0][1] = fma2(a2.x, b1, acc[0][1]); acc[1][1] = fma2(a2.y, b1, acc[1][1]);
        acc[0][2] = fma2(a2.x, b2, acc[0][2]); acc[1][2] = fma2(a2.y, b2, acc[1][2]);
        acc[0][3] = fma2(a2.x, b3, acc[0][3]); acc[1][3] = fma2(a2.y, b3, acc[1][3]);
    }
}

#define STS8A(buf, v0, v1) { \
    As[buf][lk+0][lrow]=v0.x; As[buf][lk+1][lrow]=v0.y; As[buf][lk+2][lrow]=v0.z; As[buf][lk+3][lrow]=v0.w; \
    As[buf][lk+4][lrow]=v1.x; As[buf][lk+5][lrow]=v1.y; As[buf][lk+6][lrow]=v1.z; As[buf][lk+7][lrow]=v1.w; }
#define STS8B(buf, v0, v1) { \
    Bs[buf][lk+0][lrow]=v0.x; Bs[buf][lk+1][lrow]=v0.y; Bs[buf][lk+2][lrow]=v0.z; Bs[buf][lk+3][lrow]=v0.w; \
    Bs[buf][lk+4][lrow]=v1.x; Bs[buf][lk+5][lrow]=v1.y; Bs[buf][lk+6][lrow]=v1.z; Bs[buf][lk+7][lrow]=v1.w; }

// ---------------- QKV projection NT GEMM, grid (8,8,3) ----------------
__global__ __launch_bounds__(256, 2) void qkv_kernel(
    const float* __restrict__ query, const float* __restrict__ key, const float* __restrict__ value,
    const float* __restrict__ Wq, const float* __restrict__ bq,
    const float* __restrict__ Wk, const float* __restrict__ bk,
    const float* __restrict__ Wv, const float* __restrict__ bv)
{
    int z = blockIdx.z;
    const float* X    = (z == 0) ? query : (z == 1) ? key : value;
    const float* W    = (z == 0) ? Wq    : (z == 1) ? Wk  : Wv;
    const float* bias = (z == 0) ? bq    : (z == 1) ? bk  : bv;

    __shared__ __align__(16) float As[2][32][68];
    __shared__ __align__(16) float Bs[2][32][68];

    int tid = threadIdx.x;
    int m0 = blockIdx.y * 64, n0 = blockIdx.x * 64;
    int lrow = tid >> 2, lk = (tid & 3) * 8;
    int ty4 = (tid >> 4) * 4, tx4 = (tid & 15) * 4;

    const float* Arow = X + (m0 + lrow) * HH + lk;
    const float* Brow = W + (n0 + lrow) * HH + lk;
    float4 ra0 = *(const float4*)(Arow),     ra1 = *(const float4*)(Arow + 4);
    float4 rb0 = *(const float4*)(Brow),     rb1 = *(const float4*)(Brow + 4);

    u64 acc[2][4];
#pragma unroll
    for (int p = 0; p < 2; p++)
#pragma unroll
        for (int j = 0; j < 4; j++) acc[p][j] = 0ull;

#pragma unroll 1
    for (int s = 0; s < 16; s++) {
        int buf = s & 1;
        STS8A(buf, ra0, ra1); STS8B(buf, rb0, rb1);
        __syncthreads();
        if (s + 1 < 16) {
            ra0 = *(const float4*)(Arow + (s+1)*32);  ra1 = *(const float4*)(Arow + (s+1)*32 + 4);
            rb0 = *(const float4*)(Brow + (s+1)*32);  rb1 = *(const float4*)(Brow + (s+1)*32 + 4);
        }
        mma32(As[buf], Bs[buf], ty4, tx4, acc);
    }

#pragma unroll
    for (int p = 0; p < 2; p++)
#pragma unroll
        for (int j = 0; j < 4; j++) {
            float2 t = unpack2(acc[p][j]);
            int c = n0 + tx4 + j;
            float bb = bias[c];
            int n_ = c >> 6, d_ = c & 63;
#pragma unroll
            for (int e = 0; e < 2; e++) {
                int m = m0 + ty4 + 2*p + e;
                int b_ = m >> 8, l_ = m & 255;
                size_t idx = ((size_t)(b_*NHH + n_)*LL + l_)*DHH + d_;
                float v = ((e == 0) ? t.x : t.y) + bb;
                if (z == 0)      g_qt[idx] = v;
                else if (z == 1) g_kt[idx] = v;
                else             g_vt[idx] = v;
            }
        }
}

// ---------------- W2 GEMM (double-buffered): g_w2[b,q,n,h], grid (8,8,8) ----------------
__global__ __launch_bounds__(256, 2) void w2_kernel(const float* __restrict__ Wr,
                                                    const float* __restrict__ v_bias)
{
    int n = blockIdx.z;
    int m0 = blockIdx.y * 64, h0 = blockIdx.x * 64;

    __shared__ __align__(16) float As[2][32][68];
    __shared__ __align__(16) float Bs[2][32][68];

    int tid = threadIdx.x;
    int lrow = tid >> 2, lk = (tid & 3) * 8;
    int brow = tid >> 3, bcol = (tid & 7) * 8;
    int ty4 = (tid >> 4) * 4, tx4 = (tid & 15) * 4;

    int m = m0 + lrow; int b_ = m >> 8, q_ = m & 255;
    const float* Arow = g_qt + ((size_t)(b_*NHH + n)*LL + q_)*DHH + lk;
    const float* Vrow = v_bias + n*DHH + lk;
    const float* Brow = Wr + (size_t)(n*DHH + brow)*HH + h0 + bcol;

    float4 ra0 = *(const float4*)(Arow),  ra1 = *(const float4*)(Arow + 4);
    float4 u0  = *(const float4*)(Vrow),  u1  = *(const float4*)(Vrow + 4);
    ra0.x += u0.x; ra0.y += u0.y; ra0.z += u0.z; ra0.w += u0.w;
    ra1.x += u1.x; ra1.y += u1.y; ra1.z += u1.z; ra1.w += u1.w;
    float4 rb0 = *(const float4*)(Brow),  rb1 = *(const float4*)(Brow + 4);

    u64 acc[2][4];
#pragma unroll
    for (int p = 0; p < 2; p++)
#pragma unroll
        for (int j = 0; j < 4; j++) acc[p][j] = 0ull;

#pragma unroll 1
    for (int s = 0; s < 2; s++) {
        int buf = s & 1;
        STS8A(buf, ra0, ra1);
        *(float4*)&Bs[buf][brow][bcol]     = rb0;
        *(float4*)&Bs[buf][brow][bcol + 4] = rb1;
        __syncthreads();
        if (s == 0) {
            ra0 = *(const float4*)(Arow + 32); ra1 = *(const float4*)(Arow + 36);
            float4 w0 = *(const float4*)(Vrow + 32), w1 = *(const float4*)(Vrow + 36);
            ra0.x += w0.x; ra0.y += w0.y; ra0.z += w0.z; ra0.w += w0.w;
            ra1.x += w1.x; ra1.y += w1.y; ra1.z += w1.z; ra1.w += w1.w;
            rb0 = *(const float4*)(Brow + 32*HH); rb1 = *(const float4*)(Brow + 32*HH + 4);
        }
        mma32(As[buf], Bs[buf], ty4, tx4, acc);
    }

#pragma unroll
    for (int p = 0; p < 2; p++)
#pragma unroll
        for (int j = 0; j < 4; j++) {
            float2 t = unpack2(acc[p][j]);
            int h = h0 + tx4 + j;
            int mm = m0 + ty4 + 2*p;
            int bb_ = mm >> 8, qq_ = mm & 255;
            g_w2[((size_t)(bb_*LL + qq_)*NHH + n)*HH + h] = t.x;
            int mm2 = mm + 1;
            int bb2 = mm2 >> 8, qq2 = mm2 & 255;
            g_w2[((size_t)(bb2*LL + qq2)*NHH + n)*HH + h] = t.y;
        }
}

// ---------------- A_C GEMM: g_ac[bn,q,k] = (qt+u) @ kt^T, grid (4,4,16) ----------------
__global__ __launch_bounds__(256, 2) void ac_kernel(const float* __restrict__ u_bias)
{
    int bn = blockIdx.z;
    int q0 = blockIdx.y * 64, k0 = blockIdx.x * 64;
    int n = bn & 7;

    __shared__ __align__(16) float As[2][32][68];
    __shared__ __align__(16) float Bs[2][32][68];

    int tid = threadIdx.x;
    int lrow = tid >> 2, lk = (tid & 3) * 8;
    int ty4 = (tid >> 4) * 4, tx4 = (tid & 15) * 4;

    const float* Arow = g_qt + ((size_t)bn*LL + q0 + lrow)*DHH + lk;
    const float* Brow = g_kt + ((size_t)bn*LL + k0 + lrow)*DHH + lk;
    const float* Urow = u_bias + n*DHH + lk;

    float4 ra0 = *(const float4*)(Arow),  ra1 = *(const float4*)(Arow + 4);
    float4 u0  = *(const float4*)(Urow),  u1  = *(const float4*)(Urow + 4);
    ra0.x += u0.x; ra0.y += u0.y; ra0.z += u0.z; ra0.w += u0.w;
    ra1.x += u1.x; ra1.y += u1.y; ra1.z += u1.z; ra1.w += u1.w;
    float4 rb0 = *(const float4*)(Brow),  rb1 = *(const float4*)(Brow + 4);

    u64 acc[2][4];
#pragma unroll
    for (int p = 0; p < 2; p++)
#pragma unroll
        for (int j = 0; j < 4; j++) acc[p][j] = 0ull;

#pragma unroll 1
    for (int s = 0; s < 2; s++) {
        int buf = s & 1;
        STS8A(buf, ra0, ra1); STS8B(buf, rb0, rb1);
        __syncthreads();
        if (s == 0) {
            ra0 = *(const float4*)(Arow + 32); ra1 = *(const float4*)(Arow + 36);
            float4 w0 = *(const float4*)(Urow + 32), w1 = *(const float4*)(Urow + 36);
            ra0.x += w0.x; ra0.y += w0.y; ra0.z += w0.z; ra0.w += w0.w;
            ra1.x += w1.x; ra1.y += w1.y; ra1.z += w1.z; ra1.w += w1.w;
            rb0 = *(const float4*)(Brow + 32); rb1 = *(const float4*)(Brow + 36);
        }
        mma32(As[buf], Bs[buf], ty4, tx4, acc);
    }

#pragma unroll
    for (int p = 0; p < 2; p++) {
        float2 t0 = unpack2(acc[p][0]), t1 = unpack2(acc[p][1]);
        float2 t2 = unpack2(acc[p][2]), t3 = unpack2(acc[p][3]);
        int q = q0 + ty4 + 2*p;
        *(float4*)&g_ac[((size_t)bn*LL + q)  *LL + k0 + tx4] = make_float4(t0.x, t1.x, t2.x, t3.x);
        *(float4*)&g_ac[((size_t)bn*LL + q+1)*LL + k0 + tx4] = make_float4(t0.y, t1.y, t2.y, t3.y);
    }
}

// ---------------- B_D + softmax: 512 thr, h-split warp pairs, 16 warps, grid (256,2) ----------------
// warp (pair, half): k-rows pair*32..+31, h in [half*256, half*256+256)
// dyn smem: 16 warps * 8 slots * 1KB = 128KB
__global__ __launch_bounds__(512, 1) void bd_kernel(
    const float* __restrict__ rel,
    const int* __restrict__ seq_len, const int* __restrict__ lex_num)
{
    extern __shared__ __align__(16) float ring[];      // [16 warps][8 slots][256 floats]
    __shared__ __align__(16) float ssp[2][NHH * 260];  // partial scores per h-half

    int q = blockIdx.x, b = blockIdx.y;
    int tid = threadIdx.x, w = tid >> 5, lane = tid & 31;
    int pair = w >> 1, half = w & 1;
    int k0 = pair * 32;

    // zero partial-score arrays
    for (int i = tid; i < 2 * NHH * 260; i += 512) ((float*)ssp)[i] = 0.f;

    // w2 half-slice into registers: w2u[j][n] covers h = half*256 + j*128 + lane*4 .. +3
    const float* w2p = g_w2 + (size_t)(b*LL + q)*NHH*HH + half*256;
    ulonglong2 w2u[2][8];
#pragma unroll
    for (int j = 0; j < 2; j++)
#pragma unroll
        for (int n = 0; n < 8; n++)
            w2u[j][n] = *(const ulonglong2*)&w2p[n*HH + j*128 + lane*4];

    const float* relbase = rel + ((size_t)(b*LL + q)*LL + k0)*HH + half*256 + lane*4;
    float* myring = ring + w*8*256;
    uint32_t rbase = smem_u32(myring) + lane*16;

#define ISSUE_ROW(r) { const float* s_ = relbase + (size_t)(r)*HH; uint32_t d_ = rbase + ((r) & 7)*1024u; \
    CP_ASYNC16(d_, s_); CP_ASYNC16(d_ + 512, s_ + 128); CP_COMMIT(); }

    ISSUE_ROW(0); ISSUE_ROW(1); ISSUE_ROW(2); ISSUE_ROW(3);
    __syncthreads();   // ssp zeroing visible

#pragma unroll 1
    for (int r = 0; r < 32; r++) {
        if (r + 4 < 32) { ISSUE_ROW(r + 4); } else { CP_COMMIT(); }
        CP_WAIT4();

        const float* slot = myring + (r & 7)*256;
        ulonglong2 rv0 = *(const ulonglong2*)&slot[lane*4];
        ulonglong2 rv1 = *(const ulonglong2*)&slot[128 + lane*4];

        u64 p[8];
#pragma unroll
        for (int n = 0; n < 8; n++) {
            u64 acc = fma2(w2u[0][n].x, rv0.x, 0ull);
            acc = fma2(w2u[0][n].y, rv0.y, acc);
            acc = fma2(w2u[1][n].x, rv1.x, acc);
            acc = fma2(w2u[1][n].y, rv1.y, acc);
            p[n] = acc;
        }

        // butterfly: head n lands on lanes 4n..4n+3
        bool h16 = (lane & 16) != 0;
        float a[4];
#pragma unroll
        for (int t = 0; t < 4; t++) {
            float2 tl = unpack2(p[t]), th = unpack2(p[t+4]);
            float sl = tl.x + tl.y, sh = th.x + th.y;
            float keep = h16 ? sh : sl, send = h16 ? sl : sh;
            a[t] = keep + __shfl_xor_sync(0xffffffffu, send, 16);
        }
        bool h8 = (lane & 8) != 0;
        float c[2];
#pragma unroll
        for (int t = 0; t < 2; t++) {
            float keep = h8 ? a[t+2] : a[t], send = h8 ? a[t] : a[t+2];
            c[t] = keep + __shfl_xor_sync(0xffffffffu, send, 8);
        }
        bool h4 = (lane & 4) != 0;
        float keep = h4 ? c[1] : c[0], send = h4 ? c[0] : c[1];
        float e = keep + __shfl_xor_sync(0xffffffffu, send, 4);
        e += __shfl_xor_sync(0xffffffffu, e, 2);
        e += __shfl_xor_sync(0xffffffffu, e, 1);
        if ((lane & 3) == 0)
            ssp[half][(lane >> 2)*260 + k0 + r] += e;
    }
    __syncthreads();

    // softmax: warps 0..7 each handle head w (warps 8..15 idle)
    if (w < 8) {
        int total = seq_len[b] + lex_num[b];
        const float* acp = g_ac + ((size_t)(b*NHH + w)*LL + q)*LL + lane*8;
        float4 a0 = *(const float4*)(acp);
        float4 a1 = *(const float4*)(acp + 4);
        float v[8];
        v[0]=a0.x; v[1]=a0.y; v[2]=a0.z; v[3]=a0.w;
        v[4]=a1.x; v[5]=a1.y; v[6]=a1.z; v[7]=a1.w;
#pragma unroll
        for (int t = 0; t < 8; t++) {
            int kidx = lane*8 + t;
            float s = v[t] + ssp[0][w*260 + kidx] + ssp[1][w*260 + kidx];
            v[t] = (kidx < total) ? s * 0.125f : -1e15f;
        }
        float mx = v[0];
#pragma unroll
        for (int t = 1; t < 8; t++) mx = fmaxf(mx, v[t]);
#pragma unroll
        for (int sft = 16; sft > 0; sft >>= 1) mx = fmaxf(mx, __shfl_xor_sync(0xffffffffu, mx, sft));
        float sum = 0.f;
#pragma unroll
        for (int t = 0; t < 8; t++) { v[t] = expf(v[t] - mx); sum += v[t]; }
#pragma unroll
        for (int sft = 16; sft > 0; sft >>= 1) sum += __shfl_xor_sync(0xffffffffu, sum, sft);
        float inv = 1.0f / sum;
#pragma unroll
        for (int t = 0; t < 8; t++) v[t] *= inv;
        float* op = g_attn + ((size_t)(b*NHH + w)*LL + q)*LL + lane*8;
        *(float4*)(op)     = make_float4(v[0], v[1], v[2], v[3]);
        *(float4*)(op + 4) = make_float4(v[4], v[5], v[6], v[7]);
    }
}

// ---------------- AV GEMM (NN): g_pre = attn @ v, grid (4,16) ----------------
__global__ __launch_bounds__(256, 2) void av_kernel()
{
    int q0 = blockIdx.x * 64, bn = blockIdx.y;
    int b = bn >> 3, n = bn & 7;

    __shared__ __align__(16) float As[2][32][68];
    __shared__ __align__(16) float Bs[2][32][68];

    int tid = threadIdx.x;
    int lrow = tid >> 2, lk = (tid & 3) * 8;
    int brow = tid >> 3, bcol = (tid & 7) * 8;
    int ty4 = (tid >> 4) * 4, tx4 = (tid & 15) * 4;

    const float* Arow = g_attn + ((size_t)bn*LL + q0 + lrow)*LL + lk;
    const float* Brow = g_vt   + (size_t)bn*LL*DHH + brow*DHH + bcol;

    float4 ra0 = *(const float4*)(Arow),  ra1 = *(const float4*)(Arow + 4);
    float4 rb0 = *(const float4*)(Brow),  rb1 = *(const float4*)(Brow + 4);

    u64 acc[2][4];
#pragma unroll
    for (int p = 0; p < 2; p++)
#pragma unroll
        for (int j = 0; j < 4; j++) acc[p][j] = 0ull;

#pragma unroll 1
    for (int s = 0; s < 8; s++) {
        int buf = s & 1;
        STS8A(buf, ra0, ra1);
        *(float4*)&Bs[buf][brow][bcol]     = rb0;
        *(float4*)&Bs[buf][brow][bcol + 4] = rb1;
        __syncthreads();
        if (s + 1 < 8) {
            ra0 = *(const float4*)(Arow + (s+1)*32);            ra1 = *(const float4*)(Arow + (s+1)*32 + 4);
            rb0 = *(const float4*)(Brow + (s+1)*32*DHH);        rb1 = *(const float4*)(Brow + (s+1)*32*DHH + 4);
        }
        mma32(As[buf], Bs[buf], ty4, tx4, acc);
    }

#pragma unroll
    for (int p = 0; p < 2; p++)
#pragma unroll
        for (int j = 0; j < 4; j++) {
            float2 t = unpack2(acc[p][j]);
            int d = tx4 + j;
            int q = q0 + ty4 + 2*p;
            g_pre[((size_t)(b*LL + q))    *HH + n*DHH + d] = t.x;
            g_pre[((size_t)(b*LL + q + 1))*HH + n*DHH + d] = t.y;
        }
}

// ---------------- final NT GEMM: out = g_pre @ Wf^T + bf, grid (8,8) ----------------
__global__ __launch_bounds__(256, 2) void wf_kernel(const float* __restrict__ Wf,
                                                    const float* __restrict__ bf,
                                                    float* __restrict__ out)
{
    __shared__ __align__(16) float As[2][32][68];
    __shared__ __align__(16) float Bs[2][32][68];

    int tid = threadIdx.x;
    int m0 = blockIdx.y * 64, n0 = blockIdx.x * 64;
    int lrow = tid >> 2, lk = (tid & 3) * 8;
    int ty4 = (tid >> 4) * 4, tx4 = (tid & 15) * 4;

    const float* Arow = g_pre + (m0 + lrow)*HH + lk;
    const float* Brow = Wf    + (n0 + lrow)*HH + lk;
    float4 ra0 = *(const float4*)(Arow),  ra1 = *(const float4*)(Arow + 4);
    float4 rb0 = *(const float4*)(Brow),  rb1 = *(const float4*)(Brow + 4);

    u64 acc[2][4];
#pragma unroll
    for (int p = 0; p < 2; p++)
#pragma unroll
        for (int j = 0; j < 4; j++) acc[p][j] = 0ull;

#pragma unroll 1
    for (int s = 0; s < 16; s++) {
        int buf = s & 1;
        STS8A(buf, ra0, ra1); STS8B(buf, rb0, rb1);
        __syncthreads();
        if (s + 1 < 16) {
            ra0 = *(const float4*)(Arow + (s+1)*32);  ra1 = *(const float4*)(Arow + (s+1)*32 + 4);
            rb0 = *(const float4*)(Brow + (s+1)*32);  rb1 = *(const float4*)(Brow + (s+1)*32 + 4);
        }
        mma32(As[buf], Bs[buf], ty4, tx4, acc);
    }

#pragma unroll
    for (int p = 0; p < 2; p++)
#pragma unroll
        for (int j = 0; j < 4; j++) {
            float2 t = unpack2(acc[p][j]);
            int c = n0 + tx4 + j;
            float bb = bf[c];
            int m = m0 + ty4 + 2*p;
            out[(size_t)m*HH + c]     = t.x + bb;
            out[(size_t)(m+1)*HH + c] = t.y + bb;
        }
}

// ---------------- launch ----------------
extern "C" void kernel_launch(void* const* d_in, const int* in_sizes, int n_in,
                              void* d_out, int out_size) {
    (void)in_sizes; (void)n_in; (void)out_size;
    const float* key     = (const float*)d_in[0];
    const float* query   = (const float*)d_in[1];
    const float* value   = (const float*)d_in[2];
    const float* rel     = (const float*)d_in[3];
    const float* Wk      = (const float*)d_in[4];
    const float* bk      = (const float*)d_in[5];
    const float* Wq      = (const float*)d_in[6];
    const float* bq      = (const float*)d_in[7];
    const float* Wv      = (const float*)d_in[8];
    const float* bv      = (const float*)d_in[9];
    const float* Wr      = (const float*)d_in[10];
    // d_in[11] = br: constant per score row -> cancels in softmax
    const float* u_bias  = (const float*)d_in[12];
    const float* v_bias  = (const float*)d_in[13];
    const float* Wf      = (const float*)d_in[14];
    const float* bf      = (const float*)d_in[15];
    const int*   seq_len = (const int*)d_in[16];
    const int*   lex_num = (const int*)d_in[17];
    float* out = (float*)d_out;

    static int bd_smem_set = 0;
    if (!bd_smem_set) {
        cudaFuncSetAttribute(bd_kernel, cudaFuncAttributeMaxDynamicSharedMemorySize, 131072);
        bd_smem_set = 1;
    }

    qkv_kernel<<<dim3(8, 8, 3), 256>>>(query, key, value, Wq, bq, Wk, bk, Wv, bv);
    w2_kernel<<<dim3(8, 8, NHH), 256>>>(Wr, v_bias);
    ac_kernel<<<dim3(4, 4, 16), 256>>>(u_bias);
    bd_kernel<<<dim3(LL, BB), 512, 131072>>>(rel, seq_len, lex_num);
    av_kernel<<<dim3(4, 16), 256>>>();
    wf_kernel<<<dim3(8, 8), 256>>>(Wf, bf, out);
}

// round 14
// speedup vs baseline: 1.0250x; 1.0250x over previous
#include <cuda_runtime.h>
#include <cstdint>
#include <math.h>

typedef unsigned long long u64;

#define BB 2
#define LL 256
#define HH 512
#define NHH 8
#define DHH 64

// ---------------- device scratch ----------------
__device__ float g_qt  [BB*NHH*LL*DHH];   // [b,n,l,d]
__device__ float g_kt  [BB*NHH*LL*DHH];   // [b,n,l,d]
__device__ float g_vt  [BB*NHH*LL*DHH];   // [b,n,l,d]
__device__ float g_w2  [BB*LL*NHH*HH];    // [b,q,n,h]
__device__ float g_ac  [BB*NHH*LL*LL];    // [b,n,q,k]
__device__ float g_attn[BB*NHH*LL*LL];    // [b,n,q,k]
__device__ float g_pre [BB*LL*HH];        // [b,q, n*64+d]

// ---------------- helpers ----------------
__device__ __forceinline__ u64 fma2(u64 a, u64 b, u64 c) {
    u64 d; asm("fma.rn.f32x2 %0, %1, %2, %3;" : "=l"(d) : "l"(a), "l"(b), "l"(c)); return d;
}
__device__ __forceinline__ u64 pack2(float x, float y) {
    u64 r; asm("mov.b64 %0, {%1, %2};" : "=l"(r) : "f"(x), "f"(y)); return r;
}
__device__ __forceinline__ float2 unpack2(u64 v) {
    float2 r; asm("mov.b64 {%0, %1}, %2;" : "=f"(r.x), "=f"(r.y) : "l"(v)); return r;
}
__device__ __forceinline__ uint32_t smem_u32(const void* p) {
    return (uint32_t)__cvta_generic_to_shared(p);
}
__device__ __forceinline__ uint32_t to_tf32(float f) {
    uint32_t t; asm("cvt.rna.tf32.f32 %0, %1;" : "=r"(t) : "f"(f)); return t;
}

#define CP_ASYNC16(dst, src) asm volatile("cp.async.cg.shared.global [%0], [%1], 16;" :: "r"(dst), "l"(src))
#define CP_COMMIT()          asm volatile("cp.async.commit_group;")
#define CP_WAIT2()           asm volatile("cp.async.wait_group 2;")

// ---------------- shared 64x64 mma inner (32-k step) ----------------
__device__ __forceinline__ void mma32(const float (*As)[68], const float (*Bs)[68],
                                      int ty4, int tx4, u64 acc[2][4]) {
#pragma unroll
    for (int kk = 0; kk < 32; kk++) {
        ulonglong2 a2 = *(const ulonglong2*)&As[kk][ty4];
        float4 bv = *(const float4*)&Bs[kk][tx4];
        u64 b0 = pack2(bv.x, bv.x), b1 = pack2(bv.y, bv.y);
        u64 b2 = pack2(bv.z, bv.z), b3 = pack2(bv.w, bv.w);
        acc[0][0] = fma2(a2.x, b0, acc[0][0]); acc[1][0] = fma2(a2.y, b0, acc[1][0]);
        acc[0][1] = fma2(a2.x, b1, acc[0][1]); acc[1][1] = fma2(a2.y, b1, acc[1][1]);
        acc[0][2] = fma2(a2.x, b2, acc[0][2]); acc[1][2] = fma2(a2.y, b2, acc[1][2]);
        acc[0][3] = fma2(a2.x, b3, acc[0][3]); acc[1][3] = fma2(a2.y, b3, acc[1][3]);
    }
}

#define STS8A(buf, v0, v1) { \
    As[buf][lk+0][lrow]=v0.x; As[buf][lk+1][lrow]=v0.y; As[buf][lk+2][lrow]=v0.z; As[buf][lk+3][lrow]=v0.w; \
    As[buf][lk+4][lrow]=v1.x; As[buf][lk+5][lrow]=v1.y; As[buf][lk+6][lrow]=v1.z; As[buf][lk+7][lrow]=v1.w; }
#define STS8B(buf, v0, v1) { \
    Bs[buf][lk+0][lrow]=v0.x; Bs[buf][lk+1][lrow]=v0.y; Bs[buf][lk+2][lrow]=v0.z; Bs[buf][lk+3][lrow]=v0.w; \
    Bs[buf][lk+4][lrow]=v1.x; Bs[buf][lk+5][lrow]=v1.y; Bs[buf][lk+6][lrow]=v1.z; Bs[buf][lk+7][lrow]=v1.w; }

// ---------------- QKV projection NT GEMM, grid (8,8,3) ----------------
__global__ __launch_bounds__(256, 2) void qkv_kernel(
    const float* __restrict__ query, const float* __restrict__ key, const float* __restrict__ value,
    const float* __restrict__ Wq, const float* __restrict__ bq,
    const float* __restrict__ Wk, const float* __restrict__ bk,
    const float* __restrict__ Wv, const float* __restrict__ bv)
{
    int z = blockIdx.z;
    const float* X    = (z == 0) ? query : (z == 1) ? key : value;
    const float* W    = (z == 0) ? Wq    : (z == 1) ? Wk  : Wv;
    const float* bias = (z == 0) ? bq    : (z == 1) ? bk  : bv;

    __shared__ __align__(16) float As[2][32][68];
    __shared__ __align__(16) float Bs[2][32][68];

    int tid = threadIdx.x;
    int m0 = blockIdx.y * 64, n0 = blockIdx.x * 64;
    int lrow = tid >> 2, lk = (tid & 3) * 8;
    int ty4 = (tid >> 4) * 4, tx4 = (tid & 15) * 4;

    const float* Arow = X + (m0 + lrow) * HH + lk;
    const float* Brow = W + (n0 + lrow) * HH + lk;
    float4 ra0 = *(const float4*)(Arow),     ra1 = *(const float4*)(Arow + 4);
    float4 rb0 = *(const float4*)(Brow),     rb1 = *(const float4*)(Brow + 4);

    u64 acc[2][4];
#pragma unroll
    for (int p = 0; p < 2; p++)
#pragma unroll
        for (int j = 0; j < 4; j++) acc[p][j] = 0ull;

#pragma unroll 1
    for (int s = 0; s < 16; s++) {
        int buf = s & 1;
        STS8A(buf, ra0, ra1); STS8B(buf, rb0, rb1);
        __syncthreads();
        if (s + 1 < 16) {
            ra0 = *(const float4*)(Arow + (s+1)*32);  ra1 = *(const float4*)(Arow + (s+1)*32 + 4);
            rb0 = *(const float4*)(Brow + (s+1)*32);  rb1 = *(const float4*)(Brow + (s+1)*32 + 4);
        }
        mma32(As[buf], Bs[buf], ty4, tx4, acc);
    }

#pragma unroll
    for (int p = 0; p < 2; p++)
#pragma unroll
        for (int j = 0; j < 4; j++) {
            float2 t = unpack2(acc[p][j]);
            int c = n0 + tx4 + j;
            float bb = bias[c];
            int n_ = c >> 6, d_ = c & 63;
#pragma unroll
            for (int e = 0; e < 2; e++) {
                int m = m0 + ty4 + 2*p + e;
                int b_ = m >> 8, l_ = m & 255;
                size_t idx = ((size_t)(b_*NHH + n_)*LL + l_)*DHH + d_;
                float v = ((e == 0) ? t.x : t.y) + bb;
                if (z == 0)      g_qt[idx] = v;
                else if (z == 1) g_kt[idx] = v;
                else             g_vt[idx] = v;
            }
        }
}

// ---------------- W2 GEMM (double-buffered): g_w2[b,q,n,h], grid (8,8,8) ----------------
__global__ __launch_bounds__(256, 2) void w2_kernel(const float* __restrict__ Wr,
                                                    const float* __restrict__ v_bias)
{
    int n = blockIdx.z;
    int m0 = blockIdx.y * 64, h0 = blockIdx.x * 64;

    __shared__ __align__(16) float As[2][32][68];
    __shared__ __align__(16) float Bs[2][32][68];

    int tid = threadIdx.x;
    int lrow = tid >> 2, lk = (tid & 3) * 8;
    int brow = tid >> 3, bcol = (tid & 7) * 8;
    int ty4 = (tid >> 4) * 4, tx4 = (tid & 15) * 4;

    int m = m0 + lrow; int b_ = m >> 8, q_ = m & 255;
    const float* Arow = g_qt + ((size_t)(b_*NHH + n)*LL + q_)*DHH + lk;
    const float* Vrow = v_bias + n*DHH + lk;
    const float* Brow = Wr + (size_t)(n*DHH + brow)*HH + h0 + bcol;

    float4 ra0 = *(const float4*)(Arow),  ra1 = *(const float4*)(Arow + 4);
    float4 u0  = *(const float4*)(Vrow),  u1  = *(const float4*)(Vrow + 4);
    ra0.x += u0.x; ra0.y += u0.y; ra0.z += u0.z; ra0.w += u0.w;
    ra1.x += u1.x; ra1.y += u1.y; ra1.z += u1.z; ra1.w += u1.w;
    float4 rb0 = *(const float4*)(Brow),  rb1 = *(const float4*)(Brow + 4);

    u64 acc[2][4];
#pragma unroll
    for (int p = 0; p < 2; p++)
#pragma unroll
        for (int j = 0; j < 4; j++) acc[p][j] = 0ull;

#pragma unroll 1
    for (int s = 0; s < 2; s++) {
        int buf = s & 1;
        STS8A(buf, ra0, ra1);
        *(float4*)&Bs[buf][brow][bcol]     = rb0;
        *(float4*)&Bs[buf][brow][bcol + 4] = rb1;
        __syncthreads();
        if (s == 0) {
            ra0 = *(const float4*)(Arow + 32); ra1 = *(const float4*)(Arow + 36);
            float4 w0 = *(const float4*)(Vrow + 32), w1 = *(const float4*)(Vrow + 36);
            ra0.x += w0.x; ra0.y += w0.y; ra0.z += w0.z; ra0.w += w0.w;
            ra1.x += w1.x; ra1.y += w1.y; ra1.z += w1.z; ra1.w += w1.w;
            rb0 = *(const float4*)(Brow + 32*HH); rb1 = *(const float4*)(Brow + 32*HH + 4);
        }
        mma32(As[buf], Bs[buf], ty4, tx4, acc);
    }

#pragma unroll
    for (int p = 0; p < 2; p++)
#pragma unroll
        for (int j = 0; j < 4; j++) {
            float2 t = unpack2(acc[p][j]);
            int h = h0 + tx4 + j;
            int mm = m0 + ty4 + 2*p;
            int bb_ = mm >> 8, qq_ = mm & 255;
            g_w2[((size_t)(bb_*LL + qq_)*NHH + n)*HH + h] = t.x;
            int mm2 = mm + 1;
            int bb2 = mm2 >> 8, qq2 = mm2 & 255;
            g_w2[((size_t)(bb2*LL + qq2)*NHH + n)*HH + h] = t.y;
        }
}

// ---------------- A_C GEMM: g_ac[bn,q,k] = (qt+u) @ kt^T, grid (4,4,16) ----------------
__global__ __launch_bounds__(256, 2) void ac_kernel(const float* __restrict__ u_bias)
{
    int bn = blockIdx.z;
    int q0 = blockIdx.y * 64, k0 = blockIdx.x * 64;
    int n = bn & 7;

    __shared__ __align__(16) float As[2][32][68];
    __shared__ __align__(16) float Bs[2][32][68];

    int tid = threadIdx.x;
    int lrow = tid >> 2, lk = (tid & 3) * 8;
    int ty4 = (tid >> 4) * 4, tx4 = (tid & 15) * 4;

    const float* Arow = g_qt + ((size_t)bn*LL + q0 + lrow)*DHH + lk;
    const float* Brow = g_kt + ((size_t)bn*LL + k0 + lrow)*DHH + lk;
    const float* Urow = u_bias + n*DHH + lk;

    float4 ra0 = *(const float4*)(Arow),  ra1 = *(const float4*)(Arow + 4);
    float4 u0  = *(const float4*)(Urow),  u1  = *(const float4*)(Urow + 4);
    ra0.x += u0.x; ra0.y += u0.y; ra0.z += u0.z; ra0.w += u0.w;
    ra1.x += u1.x; ra1.y += u1.y; ra1.z += u1.z; ra1.w += u1.w;
    float4 rb0 = *(const float4*)(Brow),  rb1 = *(const float4*)(Brow + 4);

    u64 acc[2][4];
#pragma unroll
    for (int p = 0; p < 2; p++)
#pragma unroll
        for (int j = 0; j < 4; j++) acc[p][j] = 0ull;

#pragma unroll 1
    for (int s = 0; s < 2; s++) {
        int buf = s & 1;
        STS8A(buf, ra0, ra1); STS8B(buf, rb0, rb1);
        __syncthreads();
        if (s == 0) {
            ra0 = *(const float4*)(Arow + 32); ra1 = *(const float4*)(Arow + 36);
            float4 w0 = *(const float4*)(Urow + 32), w1 = *(const float4*)(Urow + 36);
            ra0.x += w0.x; ra0.y += w0.y; ra0.z += w0.z; ra0.w += w0.w;
            ra1.x += w1.x; ra1.y += w1.y; ra1.z += w1.z; ra1.w += w1.w;
            rb0 = *(const float4*)(Brow + 32); rb1 = *(const float4*)(Brow + 36);
        }
        mma32(As[buf], Bs[buf], ty4, tx4, acc);
    }

#pragma unroll
    for (int p = 0; p < 2; p++) {
        float2 t0 = unpack2(acc[p][0]), t1 = unpack2(acc[p][1]);
        float2 t2 = unpack2(acc[p][2]), t3 = unpack2(acc[p][3]);
        int q = q0 + ty4 + 2*p;
        *(float4*)&g_ac[((size_t)bn*LL + q)  *LL + k0 + tx4] = make_float4(t0.x, t1.x, t2.x, t3.x);
        *(float4*)&g_ac[((size_t)bn*LL + q+1)*LL + k0 + tx4] = make_float4(t0.y, t1.y, t2.y, t3.y);
    }
}

// ---------------- B_D via mma.sync tf32 + softmax, grid (256,2), 256 thr ----------------
// per CTA (b,q): S[k=256, n=8] = rel_q[256,512] @ W2_q[8,512]^T
// warp w owns k-rows w*32..+31 (two m16 tiles); h streamed in 32-float chunks,
// 4-buffer cp.async ring, C accumulators live in registers. No barriers in loop.
#define BD_ROW_PITCH 144u                   // 36 floats; bank = (4*row + col) % 32
#define BD_WARP_STRIDE 4608u                // 32 * 144
#define BD_BUF_STRIDE 36864u                // 8 warps * 4608
#define BD_W2_OFF 147456u                   // 4 buffers
#define BD_W2_PITCH 516                     // floats; bank = (4n + h) % 32
#define BD_DYN_TOTAL (147456 + 8*516*4)     // 163968

__global__ __launch_bounds__(256, 1) void bd_kernel(
    const float* __restrict__ rel,
    const int* __restrict__ seq_len, const int* __restrict__ lex_num)
{
    extern __shared__ __align__(16) char dynsm[];
    __shared__ __align__(16) float ss[NHH * 260];

    int q = blockIdx.x, b = blockIdx.y;
    int tid = threadIdx.x, w = tid >> 5, lane = tid & 31;
    int g = lane >> 2, tg = lane & 3;

    float* w2s = (float*)(dynsm + BD_W2_OFF);
    {
        const float* w2p = g_w2 + (size_t)(b*LL + q)*NHH*HH;
#pragma unroll
        for (int p = 0; p < 16; p++) {
            int i = tid + p*256;
            int n_ = i >> 9, h_ = i & 511;
            w2s[n_*BD_W2_PITCH + h_] = __uint_as_float(to_tf32(w2p[i]));
        }
    }

    const float* relq = rel + ((size_t)(b*LL + q)*LL + w*32)*HH;
    uint32_t mybuf = smem_u32(dynsm) + w*BD_WARP_STRIDE;

#define BD_LOAD(c) { \
    uint32_t dst_ = mybuf + ((uint32_t)((c) & 3))*BD_BUF_STRIDE; \
    const float* src_ = relq + (c)*32; \
    _Pragma("unroll") \
    for (int p_ = 0; p_ < 8; p_++) { \
        int li_ = p_*32 + lane; int rr_ = li_ >> 3, j_ = li_ & 7; \
        CP_ASYNC16(dst_ + rr_*BD_ROW_PITCH + j_*16u, src_ + (size_t)rr_*HH + j_*4); \
    } \
    CP_COMMIT(); }

    BD_LOAD(0); BD_LOAD(1); BD_LOAD(2);
    __syncthreads();   // w2s visible to all warps

    float cc[2][4];
#pragma unroll
    for (int t = 0; t < 2; t++)
#pragma unroll
        for (int j = 0; j < 4; j++) cc[t][j] = 0.f;

#pragma unroll 1
    for (int i = 0; i < 16; i++) {
        CP_WAIT2();                          // chunk i landed
        if (i + 3 < 16) { BD_LOAD(i + 3); } else { CP_COMMIT(); }

        const float* bufp = (const float*)(dynsm + (size_t)(i & 3)*BD_BUF_STRIDE
                                                 + (size_t)w*BD_WARP_STRIDE);
#pragma unroll
        for (int s = 0; s < 4; s++) {
            int hg = i*32 + s*8;
            uint32_t b0 = __float_as_uint(w2s[g*BD_W2_PITCH + hg + tg]);
            uint32_t b1 = __float_as_uint(w2s[g*BD_W2_PITCH + hg + tg + 4]);
#pragma unroll
            for (int t = 0; t < 2; t++) {
                const float* ap = bufp + (t*16 + g)*36 + s*8 + tg;
                uint32_t a0 = to_tf32(ap[0]);
                uint32_t a1 = to_tf32(ap[8*36]);
                uint32_t a2 = to_tf32(ap[4]);
                uint32_t a3 = to_tf32(ap[8*36 + 4]);
                asm volatile(
                    "mma.sync.aligned.m16n8k8.row.col.f32.tf32.tf32.f32 "
                    "{%0,%1,%2,%3}, {%4,%5,%6,%7}, {%8,%9}, {%0,%1,%2,%3};"
                    : "+f"(cc[t][0]), "+f"(cc[t][1]), "+f"(cc[t][2]), "+f"(cc[t][3])
                    : "r"(a0), "r"(a1), "r"(a2), "r"(a3), "r"(b0), "r"(b1));
            }
        }
    }

    // scatter C frags to ss[n][k]
#pragma unroll
    for (int t = 0; t < 2; t++) {
        int k = w*32 + t*16 + g;
        int n0 = tg*2;
        ss[n0*260 + k]           = cc[t][0];
        ss[(n0 + 1)*260 + k]     = cc[t][1];
        ss[n0*260 + k + 8]       = cc[t][2];
        ss[(n0 + 1)*260 + k + 8] = cc[t][3];
    }
    __syncthreads();

    // softmax head w: ac (from gmem) + bd (from ss), mask, normalize
    int total = seq_len[b] + lex_num[b];
    {
        const float* acp = g_ac + ((size_t)(b*NHH + w)*LL + q)*LL + lane*8;
        float4 a0 = *(const float4*)(acp);
        float4 a1 = *(const float4*)(acp + 4);
        float v[8];
        v[0]=a0.x; v[1]=a0.y; v[2]=a0.z; v[3]=a0.w;
        v[4]=a1.x; v[5]=a1.y; v[6]=a1.z; v[7]=a1.w;
#pragma unroll
        for (int t = 0; t < 8; t++) {
            int kidx = lane*8 + t;
            float s = v[t] + ss[w*260 + kidx];
            v[t] = (kidx < total) ? s * 0.125f : -1e15f;
        }
        float mx = v[0];
#pragma unroll
        for (int t = 1; t < 8; t++) mx = fmaxf(mx, v[t]);
#pragma unroll
        for (int sft = 16; sft > 0; sft >>= 1) mx = fmaxf(mx, __shfl_xor_sync(0xffffffffu, mx, sft));
        float sum = 0.f;
#pragma unroll
        for (int t = 0; t < 8; t++) { v[t] = expf(v[t] - mx); sum += v[t]; }
#pragma unroll
        for (int sft = 16; sft > 0; sft >>= 1) sum += __shfl_xor_sync(0xffffffffu, sum, sft);
        float inv = 1.0f / sum;
#pragma unroll
        for (int t = 0; t < 8; t++) v[t] *= inv;
        float* op = g_attn + ((size_t)(b*NHH + w)*LL + q)*LL + lane*8;
        *(float4*)(op)     = make_float4(v[0], v[1], v[2], v[3]);
        *(float4*)(op + 4) = make_float4(v[4], v[5], v[6], v[7]);
    }
}

// ---------------- AV GEMM (NN): g_pre = attn @ v, grid (4,16) ----------------
__global__ __launch_bounds__(256, 2) void av_kernel()
{
    int q0 = blockIdx.x * 64, bn = blockIdx.y;
    int b = bn >> 3, n = bn & 7;

    __shared__ __align__(16) float As[2][32][68];
    __shared__ __align__(16) float Bs[2][32][68];

    int tid = threadIdx.x;
    int lrow = tid >> 2, lk = (tid & 3) * 8;
    int brow = tid >> 3, bcol = (tid & 7) * 8;
    int ty4 = (tid >> 4) * 4, tx4 = (tid & 15) * 4;

    const float* Arow = g_attn + ((size_t)bn*LL + q0 + lrow)*LL + lk;
    const float* Brow = g_vt   + (size_t)bn*LL*DHH + brow*DHH + bcol;

    float4 ra0 = *(const float4*)(Arow),  ra1 = *(const float4*)(Arow + 4);
    float4 rb0 = *(const float4*)(Brow),  rb1 = *(const float4*)(Brow + 4);

    u64 acc[2][4];
#pragma unroll
    for (int p = 0; p < 2; p++)
#pragma unroll
        for (int j = 0; j < 4; j++) acc[p][j] = 0ull;

#pragma unroll 1
    for (int s = 0; s < 8; s++) {
        int buf = s & 1;
        STS8A(buf, ra0, ra1);
        *(float4*)&Bs[buf][brow][bcol]     = rb0;
        *(float4*)&Bs[buf][brow][bcol + 4] = rb1;
        __syncthreads();
        if (s + 1 < 8) {
            ra0 = *(const float4*)(Arow + (s+1)*32);            ra1 = *(const float4*)(Arow + (s+1)*32 + 4);
            rb0 = *(const float4*)(Brow + (s+1)*32*DHH);        rb1 = *(const float4*)(Brow + (s+1)*32*DHH + 4);
        }
        mma32(As[buf], Bs[buf], ty4, tx4, acc);
    }

#pragma unroll
    for (int p = 0; p < 2; p++)
#pragma unroll
        for (int j = 0; j < 4; j++) {
            float2 t = unpack2(acc[p][j]);
            int d = tx4 + j;
            int q = q0 + ty4 + 2*p;
            g_pre[((size_t)(b*LL + q))    *HH + n*DHH + d] = t.x;
            g_pre[((size_t)(b*LL + q + 1))*HH + n*DHH + d] = t.y;
        }
}

// ---------------- final NT GEMM: out = g_pre @ Wf^T + bf, grid (8,8) ----------------
__global__ __launch_bounds__(256, 2) void wf_kernel(const float* __restrict__ Wf,
                                                    const float* __restrict__ bf,
                                                    float* __restrict__ out)
{
    __shared__ __align__(16) float As[2][32][68];
    __shared__ __align__(16) float Bs[2][32][68];

    int tid = threadIdx.x;
    int m0 = blockIdx.y * 64, n0 = blockIdx.x * 64;
    int lrow = tid >> 2, lk = (tid & 3) * 8;
    int ty4 = (tid >> 4) * 4, tx4 = (tid & 15) * 4;

    const float* Arow = g_pre + (m0 + lrow)*HH + lk;
    const float* Brow = Wf    + (n0 + lrow)*HH + lk;
    float4 ra0 = *(const float4*)(Arow),  ra1 = *(const float4*)(Arow + 4);
    float4 rb0 = *(const float4*)(Brow),  rb1 = *(const float4*)(Brow + 4);

    u64 acc[2][4];
#pragma unroll
    for (int p = 0; p < 2; p++)
#pragma unroll
        for (int j = 0; j < 4; j++) acc[p][j] = 0ull;

#pragma unroll 1
    for (int s = 0; s < 16; s++) {
        int buf = s & 1;
        STS8A(buf, ra0, ra1); STS8B(buf, rb0, rb1);
        __syncthreads();
        if (s + 1 < 16) {
            ra0 = *(const float4*)(Arow + (s+1)*32);  ra1 = *(const float4*)(Arow + (s+1)*32 + 4);
            rb0 = *(const float4*)(Brow + (s+1)*32);  rb1 = *(const float4*)(Brow + (s+1)*32 + 4);
        }
        mma32(As[buf], Bs[buf], ty4, tx4, acc);
    }

#pragma unroll
    for (int p = 0; p < 2; p++)
#pragma unroll
        for (int j = 0; j < 4; j++) {
            float2 t = unpack2(acc[p][j]);
            int c = n0 + tx4 + j;
            float bb = bf[c];
            int m = m0 + ty4 + 2*p;
            out[(size_t)m*HH + c]     = t.x + bb;
            out[(size_t)(m+1)*HH + c] = t.y + bb;
        }
}

// ---------------- launch ----------------
extern "C" void kernel_launch(void* const* d_in, const int* in_sizes, int n_in,
                              void* d_out, int out_size) {
    (void)in_sizes; (void)n_in; (void)out_size;
    const float* key     = (const float*)d_in[0];
    const float* query   = (const float*)d_in[1];
    const float* value   = (const float*)d_in[2];
    const float* rel     = (const float*)d_in[3];
    const float* Wk      = (const float*)d_in[4];
    const float* bk      = (const float*)d_in[5];
    const float* Wq      = (const float*)d_in[6];
    const float* bq      = (const float*)d_in[7];
    const float* Wv      = (const float*)d_in[8];
    const float* bv      = (const float*)d_in[9];
    const float* Wr      = (const float*)d_in[10];
    // d_in[11] = br: constant per score row -> cancels in softmax
    const float* u_bias  = (const float*)d_in[12];
    const float* v_bias  = (const float*)d_in[13];
    const float* Wf      = (const float*)d_in[14];
    const float* bf      = (const float*)d_in[15];
    const int*   seq_len = (const int*)d_in[16];
    const int*   lex_num = (const int*)d_in[17];
    float* out = (float*)d_out;

    static int bd_smem_set = 0;
    if (!bd_smem_set) {
        cudaFuncSetAttribute(bd_kernel, cudaFuncAttributeMaxDynamicSharedMemorySize, BD_DYN_TOTAL);
        bd_smem_set = 1;
    }

    qkv_kernel<<<dim3(8, 8, 3), 256>>>(query, key, value, Wq, bq, Wk, bk, Wv, bv);
    w2_kernel<<<dim3(8, 8, NHH), 256>>>(Wr, v_bias);
    ac_kernel<<<dim3(4, 4, 16), 256>>>(u_bias);
    bd_kernel<<<dim3(LL, BB), 256, BD_DYN_TOTAL>>>(rel, seq_len, lex_num);
    av_kernel<<<dim3(4, 16), 256>>>();
    wf_kernel<<<dim3(8, 8), 256>>>(Wf, bf, out);
}

// round 16
// speedup vs baseline: 1.0540x; 1.0283x over previous
#include <cuda_runtime.h>
#include <cstdint>
#include <math.h>

typedef unsigned long long u64;

#define BB 2
#define LL 256
#define HH 512
#define NHH 8
#define DHH 64

// ---------------- device scratch ----------------
__device__ float g_qt  [BB*NHH*LL*DHH];   // [b,n,l,d]
__device__ float g_kt  [BB*NHH*LL*DHH];   // [b,n,l,d]
__device__ float g_vt  [BB*NHH*LL*DHH];   // [b,n,l,d]
__device__ float g_w2  [BB*LL*NHH*HH];    // [b,q,n,h]
__device__ float g_ac  [BB*NHH*LL*LL];    // [b,n,q,k]
__device__ float g_attn[BB*NHH*LL*LL];    // [b,n,q,k]
__device__ float g_pre [BB*LL*HH];        // [b,q, n*64+d]

// ---------------- helpers ----------------
__device__ __forceinline__ u64 fma2(u64 a, u64 b, u64 c) {
    u64 d; asm("fma.rn.f32x2 %0, %1, %2, %3;" : "=l"(d) : "l"(a), "l"(b), "l"(c)); return d;
}
__device__ __forceinline__ u64 pack2(float x, float y) {
    u64 r; asm("mov.b64 %0, {%1, %2};" : "=l"(r) : "f"(x), "f"(y)); return r;
}
__device__ __forceinline__ float2 unpack2(u64 v) {
    float2 r; asm("mov.b64 {%0, %1}, %2;" : "=f"(r.x), "=f"(r.y) : "l"(v)); return r;
}
__device__ __forceinline__ uint32_t smem_u32(const void* p) {
    return (uint32_t)__cvta_generic_to_shared(p);
}
__device__ __forceinline__ uint32_t to_tf32(float f) {
    uint32_t t; asm("cvt.rna.tf32.f32 %0, %1;" : "=r"(t) : "f"(f)); return t;
}

#define CP_ASYNC16(dst, src) asm volatile("cp.async.cg.shared.global [%0], [%1], 16;" :: "r"(dst), "l"(src))
#define CP_COMMIT()          asm volatile("cp.async.commit_group;")
#define CP_WAIT1()           asm volatile("cp.async.wait_group 1;")

// ---------------- shared 64x64 mma inner (32-k step) ----------------
__device__ __forceinline__ void mma32(const float (*As)[68], const float (*Bs)[68],
                                      int ty4, int tx4, u64 acc[2][4]) {
#pragma unroll
    for (int kk = 0; kk < 32; kk++) {
        ulonglong2 a2 = *(const ulonglong2*)&As[kk][ty4];
        float4 bv = *(const float4*)&Bs[kk][tx4];
        u64 b0 = pack2(bv.x, bv.x), b1 = pack2(bv.y, bv.y);
        u64 b2 = pack2(bv.z, bv.z), b3 = pack2(bv.w, bv.w);
        acc[0][0] = fma2(a2.x, b0, acc[0][0]); acc[1][0] = fma2(a2.y, b0, acc[1][0]);
        acc[0][1] = fma2(a2.x, b1, acc[0][1]); acc[1][1] = fma2(a2.y, b1, acc[1][1]);
        acc[0][2] = fma2(a2.x, b2, acc[0][2]); acc[1][2] = fma2(a2.y, b2, acc[1][2]);
        acc[0][3] = fma2(a2.x, b3, acc[0][3]); acc[1][3] = fma2(a2.y, b3, acc[1][3]);
    }
}

#define STS8A(buf, v0, v1) { \
    As[buf][lk+0][lrow]=v0.x; As[buf][lk+1][lrow]=v0.y; As[buf][lk+2][lrow]=v0.z; As[buf][lk+3][lrow]=v0.w; \
    As[buf][lk+4][lrow]=v1.x; As[buf][lk+5][lrow]=v1.y; As[buf][lk+6][lrow]=v1.z; As[buf][lk+7][lrow]=v1.w; }
#define STS8B(buf, v0, v1) { \
    Bs[buf][lk+0][lrow]=v0.x; Bs[buf][lk+1][lrow]=v0.y; Bs[buf][lk+2][lrow]=v0.z; Bs[buf][lk+3][lrow]=v0.w; \
    Bs[buf][lk+4][lrow]=v1.x; Bs[buf][lk+5][lrow]=v1.y; Bs[buf][lk+6][lrow]=v1.z; Bs[buf][lk+7][lrow]=v1.w; }

// ---------------- QKV projection NT GEMM, grid (8,8,3) ----------------
__global__ __launch_bounds__(256, 2) void qkv_kernel(
    const float* __restrict__ query, const float* __restrict__ key, const float* __restrict__ value,
    const float* __restrict__ Wq, const float* __restrict__ bq,
    const float* __restrict__ Wk, const float* __restrict__ bk,
    const float* __restrict__ Wv, const float* __restrict__ bv)
{
    int z = blockIdx.z;
    const float* X    = (z == 0) ? query : (z == 1) ? key : value;
    const float* W    = (z == 0) ? Wq    : (z == 1) ? Wk  : Wv;
    const float* bias = (z == 0) ? bq    : (z == 1) ? bk  : bv;

    __shared__ __align__(16) float As[2][32][68];
    __shared__ __align__(16) float Bs[2][32][68];

    int tid = threadIdx.x;
    int m0 = blockIdx.y * 64, n0 = blockIdx.x * 64;
    int lrow = tid >> 2, lk = (tid & 3) * 8;
    int ty4 = (tid >> 4) * 4, tx4 = (tid & 15) * 4;

    const float* Arow = X + (m0 + lrow) * HH + lk;
    const float* Brow = W + (n0 + lrow) * HH + lk;
    float4 ra0 = *(const float4*)(Arow),     ra1 = *(const float4*)(Arow + 4);
    float4 rb0 = *(const float4*)(Brow),     rb1 = *(const float4*)(Brow + 4);

    u64 acc[2][4];
#pragma unroll
    for (int p = 0; p < 2; p++)
#pragma unroll
        for (int j = 0; j < 4; j++) acc[p][j] = 0ull;

#pragma unroll 1
    for (int s = 0; s < 16; s++) {
        int buf = s & 1;
        STS8A(buf, ra0, ra1); STS8B(buf, rb0, rb1);
        __syncthreads();
        if (s + 1 < 16) {
            ra0 = *(const float4*)(Arow + (s+1)*32);  ra1 = *(const float4*)(Arow + (s+1)*32 + 4);
            rb0 = *(const float4*)(Brow + (s+1)*32);  rb1 = *(const float4*)(Brow + (s+1)*32 + 4);
        }
        mma32(As[buf], Bs[buf], ty4, tx4, acc);
    }

#pragma unroll
    for (int p = 0; p < 2; p++)
#pragma unroll
        for (int j = 0; j < 4; j++) {
            float2 t = unpack2(acc[p][j]);
            int c = n0 + tx4 + j;
            float bb = bias[c];
            int n_ = c >> 6, d_ = c & 63;
#pragma unroll
            for (int e = 0; e < 2; e++) {
                int m = m0 + ty4 + 2*p + e;
                int b_ = m >> 8, l_ = m & 255;
                size_t idx = ((size_t)(b_*NHH + n_)*LL + l_)*DHH + d_;
                float v = ((e == 0) ? t.x : t.y) + bb;
                if (z == 0)      g_qt[idx] = v;
                else if (z == 1) g_kt[idx] = v;
                else             g_vt[idx] = v;
            }
        }
}

// ---------------- W2 GEMM (double-buffered): g_w2[b,q,n,h], grid (8,8,8) ----------------
__global__ __launch_bounds__(256, 2) void w2_kernel(const float* __restrict__ Wr,
                                                    const float* __restrict__ v_bias)
{
    int n = blockIdx.z;
    int m0 = blockIdx.y * 64, h0 = blockIdx.x * 64;

    __shared__ __align__(16) float As[2][32][68];
    __shared__ __align__(16) float Bs[2][32][68];

    int tid = threadIdx.x;
    int lrow = tid >> 2, lk = (tid & 3) * 8;
    int brow = tid >> 3, bcol = (tid & 7) * 8;
    int ty4 = (tid >> 4) * 4, tx4 = (tid & 15) * 4;

    int m = m0 + lrow; int b_ = m >> 8, q_ = m & 255;
    const float* Arow = g_qt + ((size_t)(b_*NHH + n)*LL + q_)*DHH + lk;
    const float* Vrow = v_bias + n*DHH + lk;
    const float* Brow = Wr + (size_t)(n*DHH + brow)*HH + h0 + bcol;

    float4 ra0 = *(const float4*)(Arow),  ra1 = *(const float4*)(Arow + 4);
    float4 u0  = *(const float4*)(Vrow),  u1  = *(const float4*)(Vrow + 4);
    ra0.x += u0.x; ra0.y += u0.y; ra0.z += u0.z; ra0.w += u0.w;
    ra1.x += u1.x; ra1.y += u1.y; ra1.z += u1.z; ra1.w += u1.w;
    float4 rb0 = *(const float4*)(Brow),  rb1 = *(const float4*)(Brow + 4);

    u64 acc[2][4];
#pragma unroll
    for (int p = 0; p < 2; p++)
#pragma unroll
        for (int j = 0; j < 4; j++) acc[p][j] = 0ull;

#pragma unroll 1
    for (int s = 0; s < 2; s++) {
        int buf = s & 1;
        STS8A(buf, ra0, ra1);
        *(float4*)&Bs[buf][brow][bcol]     = rb0;
        *(float4*)&Bs[buf][brow][bcol + 4] = rb1;
        __syncthreads();
        if (s == 0) {
            ra0 = *(const float4*)(Arow + 32); ra1 = *(const float4*)(Arow + 36);
            float4 w0 = *(const float4*)(Vrow + 32), w1 = *(const float4*)(Vrow + 36);
            ra0.x += w0.x; ra0.y += w0.y; ra0.z += w0.z; ra0.w += w0.w;
            ra1.x += w1.x; ra1.y += w1.y; ra1.z += w1.z; ra1.w += w1.w;
            rb0 = *(const float4*)(Brow + 32*HH); rb1 = *(const float4*)(Brow + 32*HH + 4);
        }
        mma32(As[buf], Bs[buf], ty4, tx4, acc);
    }

#pragma unroll
    for (int p = 0; p < 2; p++)
#pragma unroll
        for (int j = 0; j < 4; j++) {
            float2 t = unpack2(acc[p][j]);
            int h = h0 + tx4 + j;
            int mm = m0 + ty4 + 2*p;
            int bb_ = mm >> 8, qq_ = mm & 255;
            g_w2[((size_t)(bb_*LL + qq_)*NHH + n)*HH + h] = t.x;
            int mm2 = mm + 1;
            int bb2 = mm2 >> 8, qq2 = mm2 & 255;
            g_w2[((size_t)(bb2*LL + qq2)*NHH + n)*HH + h] = t.y;
        }
}

// ---------------- A_C GEMM: g_ac[bn,q,k] = (qt+u) @ kt^T, grid (4,4,16) ----------------
__global__ __launch_bounds__(256, 2) void ac_kernel(const float* __restrict__ u_bias)
{
    int bn = blockIdx.z;
    int q0 = blockIdx.y * 64, k0 = blockIdx.x * 64;
    int n = bn & 7;

    __shared__ __align__(16) float As[2][32][68];
    __shared__ __align__(16) float Bs[2][32][68];

    int tid = threadIdx.x;
    int lrow = tid >> 2, lk = (tid & 3) * 8;
    int ty4 = (tid >> 4) * 4, tx4 = (tid & 15) * 4;

    const float* Arow = g_qt + ((size_t)bn*LL + q0 + lrow)*DHH + lk;
    const float* Brow = g_kt + ((size_t)bn*LL + k0 + lrow)*DHH + lk;
    const float* Urow = u_bias + n*DHH + lk;

    float4 ra0 = *(const float4*)(Arow),  ra1 = *(const float4*)(Arow + 4);
    float4 u0  = *(const float4*)(Urow),  u1  = *(const float4*)(Urow + 4);
    ra0.x += u0.x; ra0.y += u0.y; ra0.z += u0.z; ra0.w += u0.w;
    ra1.x += u1.x; ra1.y += u1.y; ra1.z += u1.z; ra1.w += u1.w;
    float4 rb0 = *(const float4*)(Brow),  rb1 = *(const float4*)(Brow + 4);

    u64 acc[2][4];
#pragma unroll
    for (int p = 0; p < 2; p++)
#pragma unroll
        for (int j = 0; j < 4; j++) acc[p][j] = 0ull;

#pragma unroll 1
    for (int s = 0; s < 2; s++) {
        int buf = s & 1;
        STS8A(buf, ra0, ra1); STS8B(buf, rb0, rb1);
        __syncthreads();
        if (s == 0) {
            ra0 = *(const float4*)(Arow + 32); ra1 = *(const float4*)(Arow + 36);
            float4 w0 = *(const float4*)(Urow + 32), w1 = *(const float4*)(Urow + 36);
            ra0.x += w0.x; ra0.y += w0.y; ra0.z += w0.z; ra0.w += w0.w;
            ra1.x += w1.x; ra1.y += w1.y; ra1.z += w1.z; ra1.w += w1.w;
            rb0 = *(const float4*)(Brow + 32); rb1 = *(const float4*)(Brow + 36);
        }
        mma32(As[buf], Bs[buf], ty4, tx4, acc);
    }

#pragma unroll
    for (int p = 0; p < 2; p++) {
        float2 t0 = unpack2(acc[p][0]), t1 = unpack2(acc[p][1]);
        float2 t2 = unpack2(acc[p][2]), t3 = unpack2(acc[p][3]);
        int q = q0 + ty4 + 2*p;
        *(float4*)&g_ac[((size_t)bn*LL + q)  *LL + k0 + tx4] = make_float4(t0.x, t1.x, t2.x, t3.x);
        *(float4*)&g_ac[((size_t)bn*LL + q+1)*LL + k0 + tx4] = make_float4(t0.y, t1.y, t2.y, t3.y);
    }
}

// ---------------- B_D via mma.sync tf32 + softmax, grid (256,2), 256 thr, 2 CTAs/SM ----------------
// per CTA (b,q): S[k=256, n=8] = rel_q[256,512] @ W2_q[8,512]^T
// warp w owns k-rows w*32..+31; h streamed in 32-float chunks through a
// 2-buffer cp.async ring; fragments hoisted to regs before reissuing the buffer.
#define BD_ROW_PITCH 144u                   // 36 floats; bank = (4*row + col) % 32
#define BD_WARP_STRIDE 4608u                // 32 * 144
#define BD_BUF_STRIDE 36864u                // 8 warps * 4608
#define BD_W2_OFF 73728u                    // 2 buffers
#define BD_W2_PITCH 516                     // floats; bank = (4n + h) % 32
#define BD_DYN_TOTAL (73728 + 8*516*4)      // 90240

__global__ __launch_bounds__(256, 2) void bd_kernel(
    const float* __restrict__ rel,
    const int* __restrict__ seq_len, const int* __restrict__ lex_num)
{
    extern __shared__ __align__(16) char dynsm[];
    __shared__ __align__(16) float ss[NHH * 260];

    int q = blockIdx.x, b = blockIdx.y;
    int tid = threadIdx.x, w = tid >> 5, lane = tid & 31;
    int g = lane >> 2, tg = lane & 3;

    float* w2s = (float*)(dynsm + BD_W2_OFF);
    {
        const float* w2p = g_w2 + (size_t)(b*LL + q)*NHH*HH;
#pragma unroll
        for (int p = 0; p < 16; p++) {
            int i = tid + p*256;
            int n_ = i >> 9, h_ = i & 511;
            w2s[n_*BD_W2_PITCH + h_] = __uint_as_float(to_tf32(w2p[i]));
        }
    }

    const float* relq = rel + ((size_t)(b*LL + q)*LL + w*32)*HH;
    uint32_t mybuf = smem_u32(dynsm) + w*BD_WARP_STRIDE;

#define BD_LOAD(c) { \
    uint32_t dst_ = mybuf + ((uint32_t)((c) & 1))*BD_BUF_STRIDE; \
    const float* src_ = relq + (c)*32; \
    _Pragma("unroll") \
    for (int p_ = 0; p_ < 8; p_++) { \
        int li_ = p_*32 + lane; int rr_ = li_ >> 3, j_ = li_ & 7; \
        CP_ASYNC16(dst_ + rr_*BD_ROW_PITCH + j_*16u, src_ + (size_t)rr_*HH + j_*4); \
    } \
    CP_COMMIT(); }

    BD_LOAD(0); BD_LOAD(1);
    __syncthreads();   // w2s visible to all warps

    float cc[2][4];
#pragma unroll
    for (int t = 0; t < 2; t++)
#pragma unroll
        for (int j = 0; j < 4; j++) cc[t][j] = 0.f;

#pragma unroll 1
    for (int i = 0; i < 16; i++) {
        CP_WAIT1();                          // chunk i landed (i+1 may be pending)

        const float* bufp = (const float*)(dynsm + (size_t)(i & 1)*BD_BUF_STRIDE
                                                 + (size_t)w*BD_WARP_STRIDE);
        // hoist all fragments to registers before the buffer is reissued
        uint32_t areg[2][4][4];
        uint32_t breg[4][2];
#pragma unroll
        for (int s = 0; s < 4; s++) {
            int hg = i*32 + s*8;
            breg[s][0] = __float_as_uint(w2s[g*BD_W2_PITCH + hg + tg]);
            breg[s][1] = __float_as_uint(w2s[g*BD_W2_PITCH + hg + tg + 4]);
#pragma unroll
            for (int t = 0; t < 2; t++) {
                const float* ap = bufp + (t*16 + g)*36 + s*8 + tg;
                areg[t][s][0] = to_tf32(ap[0]);
                areg[t][s][1] = to_tf32(ap[8*36]);
                areg[t][s][2] = to_tf32(ap[4]);
                areg[t][s][3] = to_tf32(ap[8*36 + 4]);
            }
        }

        if (i + 2 < 16) { BD_LOAD(i + 2); } else { CP_COMMIT(); }

#pragma unroll
        for (int s = 0; s < 4; s++)
#pragma unroll
            for (int t = 0; t < 2; t++) {
                asm volatile(
                    "mma.sync.aligned.m16n8k8.row.col.f32.tf32.tf32.f32 "
                    "{%0,%1,%2,%3}, {%4,%5,%6,%7}, {%8,%9}, {%0,%1,%2,%3};"
                    : "+f"(cc[t][0]), "+f"(cc[t][1]), "+f"(cc[t][2]), "+f"(cc[t][3])
                    : "r"(areg[t][s][0]), "r"(areg[t][s][1]), "r"(areg[t][s][2]), "r"(areg[t][s][3]),
                      "r"(breg[s][0]), "r"(breg[s][1]));
            }
    }

    // scatter C frags to ss[n][k]
#pragma unroll
    for (int t = 0; t < 2; t++) {
        int k = w*32 + t*16 + g;
        int n0 = tg*2;
        ss[n0*260 + k]           = cc[t][0];
        ss[(n0 + 1)*260 + k]     = cc[t][1];
        ss[n0*260 + k + 8]       = cc[t][2];
        ss[(n0 + 1)*260 + k + 8] = cc[t][3];
    }
    __syncthreads();

    // softmax head w: ac (from gmem) + bd (from ss), mask, normalize
    int total = seq_len[b] + lex_num[b];
    {
        const float* acp = g_ac + ((size_t)(b*NHH + w)*LL + q)*LL + lane*8;
        float4 a0 = *(const float4*)(acp);
        float4 a1 = *(const float4*)(acp + 4);
        float v[8];
        v[0]=a0.x; v[1]=a0.y; v[2]=a0.z; v[3]=a0.w;
        v[4]=a1.x; v[5]=a1.y; v[6]=a1.z; v[7]=a1.w;
#pragma unroll
        for (int t = 0; t < 8; t++) {
            int kidx = lane*8 + t;
            float s = v[t] + ss[w*260 + kidx];
            v[t] = (kidx < total) ? s * 0.125f : -1e15f;
        }
        float mx = v[0];
#pragma unroll
        for (int t = 1; t < 8; t++) mx = fmaxf(mx, v[t]);
#pragma unroll
        for (int sft = 16; sft > 0; sft >>= 1) mx = fmaxf(mx, __shfl_xor_sync(0xffffffffu, mx, sft));
        float sum = 0.f;
#pragma unroll
        for (int t = 0; t < 8; t++) { v[t] = expf(v[t] - mx); sum += v[t]; }
#pragma unroll
        for (int sft = 16; sft > 0; sft >>= 1) sum += __shfl_xor_sync(0xffffffffu, sum, sft);
        float inv = 1.0f / sum;
#pragma unroll
        for (int t = 0; t < 8; t++) v[t] *= inv;
        float* op = g_attn + ((size_t)(b*NHH + w)*LL + q)*LL + lane*8;
        *(float4*)(op)     = make_float4(v[0], v[1], v[2], v[3]);
        *(float4*)(op + 4) = make_float4(v[4], v[5], v[6], v[7]);
    }
}

// ---------------- AV GEMM (NN): g_pre = attn @ v, grid (4,16) ----------------
__global__ __launch_bounds__(256, 2) void av_kernel()
{
    int q0 = blockIdx.x * 64, bn = blockIdx.y;
    int b = bn >> 3, n = bn & 7;

    __shared__ __align__(16) float As[2][32][68];
    __shared__ __align__(16) float Bs[2][32][68];

    int tid = threadIdx.x;
    int lrow = tid >> 2, lk = (tid & 3) * 8;
    int brow = tid >> 3, bcol = (tid & 7) * 8;
    int ty4 = (tid >> 4) * 4, tx4 = (tid & 15) * 4;

    const float* Arow = g_attn + ((size_t)bn*LL + q0 + lrow)*LL + lk;
    const float* Brow = g_vt   + (size_t)bn*LL*DHH + brow*DHH + bcol;

    float4 ra0 = *(const float4*)(Arow),  ra1 = *(const float4*)(Arow + 4);
    float4 rb0 = *(const float4*)(Brow),  rb1 = *(const float4*)(Brow + 4);

    u64 acc[2][4];
#pragma unroll
    for (int p = 0; p < 2; p++)
#pragma unroll
        for (int j = 0; j < 4; j++) acc[p][j] = 0ull;

#pragma unroll 1
    for (int s = 0; s < 8; s++) {
        int buf = s & 1;
        STS8A(buf, ra0, ra1);
        *(float4*)&Bs[buf][brow][bcol]     = rb0;
        *(float4*)&Bs[buf][brow][bcol + 4] = rb1;
        __syncthreads();
        if (s + 1 < 8) {
            ra0 = *(const float4*)(Arow + (s+1)*32);            ra1 = *(const float4*)(Arow + (s+1)*32 + 4);
            rb0 = *(const float4*)(Brow + (s+1)*32*DHH);        rb1 = *(const float4*)(Brow + (s+1)*32*DHH + 4);
        }
        mma32(As[buf], Bs[buf], ty4, tx4, acc);
    }

#pragma unroll
    for (int p = 0; p < 2; p++)
#pragma unroll
        for (int j = 0; j < 4; j++) {
            float2 t = unpack2(acc[p][j]);
            int d = tx4 + j;
            int q = q0 + ty4 + 2*p;
            g_pre[((size_t)(b*LL + q))    *HH + n*DHH + d] = t.x;
            g_pre[((size_t)(b*LL + q + 1))*HH + n*DHH + d] = t.y;
        }
}

// ---------------- final NT GEMM: out = g_pre @ Wf^T + bf, grid (8,8) ----------------
__global__ __launch_bounds__(256, 2) void wf_kernel(const float* __restrict__ Wf,
                                                    const float* __restrict__ bf,
                                                    float* __restrict__ out)
{
    __shared__ __align__(16) float As[2][32][68];
    __shared__ __align__(16) float Bs[2][32][68];

    int tid = threadIdx.x;
    int m0 = blockIdx.y * 64, n0 = blockIdx.x * 64;
    int lrow = tid >> 2, lk = (tid & 3) * 8;
    int ty4 = (tid >> 4) * 4, tx4 = (tid & 15) * 4;

    const float* Arow = g_pre + (m0 + lrow)*HH + lk;
    const float* Brow = Wf    + (n0 + lrow)*HH + lk;
    float4 ra0 = *(const float4*)(Arow),  ra1 = *(const float4*)(Arow + 4);
    float4 rb0 = *(const float4*)(Brow),  rb1 = *(const float4*)(Brow + 4);

    u64 acc[2][4];
#pragma unroll
    for (int p = 0; p < 2; p++)
#pragma unroll
        for (int j = 0; j < 4; j++) acc[p][j] = 0ull;

#pragma unroll 1
    for (int s = 0; s < 16; s++) {
        int buf = s & 1;
        STS8A(buf, ra0, ra1); STS8B(buf, rb0, rb1);
        __syncthreads();
        if (s + 1 < 16) {
            ra0 = *(const float4*)(Arow + (s+1)*32);  ra1 = *(const float4*)(Arow + (s+1)*32 + 4);
            rb0 = *(const float4*)(Brow + (s+1)*32);  rb1 = *(const float4*)(Brow + (s+1)*32 + 4);
        }
        mma32(As[buf], Bs[buf], ty4, tx4, acc);
    }

#pragma unroll
    for (int p = 0; p < 2; p++)
#pragma unroll
        for (int j = 0; j < 4; j++) {
            float2 t = unpack2(acc[p][j]);
            int c = n0 + tx4 + j;
            float bb = bf[c];
            int m = m0 + ty4 + 2*p;
            out[(size_t)m*HH + c]     = t.x + bb;
            out[(size_t)(m+1)*HH + c] = t.y + bb;
        }
}

// ---------------- launch ----------------
extern "C" void kernel_launch(void* const* d_in, const int* in_sizes, int n_in,
                              void* d_out, int out_size) {
    (void)in_sizes; (void)n_in; (void)out_size;
    const float* key     = (const float*)d_in[0];
    const float* query   = (const float*)d_in[1];
    const float* value   = (const float*)d_in[2];
    const float* rel     = (const float*)d_in[3];
    const float* Wk      = (const float*)d_in[4];
    const float* bk      = (const float*)d_in[5];
    const float* Wq      = (const float*)d_in[6];
    const float* bq      = (const float*)d_in[7];
    const float* Wv      = (const float*)d_in[8];
    const float* bv      = (const float*)d_in[9];
    const float* Wr      = (const float*)d_in[10];
    // d_in[11] = br: constant per score row -> cancels in softmax
    const float* u_bias  = (const float*)d_in[12];
    const float* v_bias  = (const float*)d_in[13];
    const float* Wf      = (const float*)d_in[14];
    const float* bf      = (const float*)d_in[15];
    const int*   seq_len = (const int*)d_in[16];
    const int*   lex_num = (const int*)d_in[17];
    float* out = (float*)d_out;

    static int bd_smem_set = 0;
    if (!bd_smem_set) {
        cudaFuncSetAttribute(bd_kernel, cudaFuncAttributeMaxDynamicSharedMemorySize, BD_DYN_TOTAL);
        bd_smem_set = 1;
    }

    qkv_kernel<<<dim3(8, 8, 3), 256>>>(query, key, value, Wq, bq, Wk, bk, Wv, bv);
    w2_kernel<<<dim3(8, 8, NHH), 256>>>(Wr, v_bias);
    ac_kernel<<<dim3(4, 4, 16), 256>>>(u_bias);
    bd_kernel<<<dim3(LL, BB), 256, BD_DYN_TOTAL>>>(rel, seq_len, lex_num);
    av_kernel<<<dim3(4, 16), 256>>>();
    wf_kernel<<<dim3(8, 8), 256>>>(Wf, bf, out);
}

// round 17
// speedup vs baseline: 1.2924x; 1.2262x over previous
#include <cuda_runtime.h>
#include <cstdint>
#include <math.h>

typedef unsigned long long u64;

#define BB 2
#define LL 256
#define HH 512
#define NHH 8
#define DHH 64

// ---------------- device scratch ----------------
__device__ float g_qt  [BB*NHH*LL*DHH];   // [b,n,l,d]
__device__ float g_kt  [BB*NHH*LL*DHH];   // [b,n,l,d]
__device__ float g_vt  [BB*NHH*LL*DHH];   // [b,n,l,d]
__device__ float g_w2  [BB*LL*NHH*HH];    // [b,q,n,h]
__device__ float g_ac  [BB*NHH*LL*LL];    // [b,n,q,k]
__device__ float g_attn[BB*NHH*LL*LL];    // [b,n,q,k]
__device__ float g_pre [BB*LL*HH];        // [b,q, n*64+d]

// ---------------- helpers ----------------
__device__ __forceinline__ u64 fma2(u64 a, u64 b, u64 c) {
    u64 d; asm("fma.rn.f32x2 %0, %1, %2, %3;" : "=l"(d) : "l"(a), "l"(b), "l"(c)); return d;
}
__device__ __forceinline__ u64 pack2(float x, float y) {
    u64 r; asm("mov.b64 %0, {%1, %2};" : "=l"(r) : "f"(x), "f"(y)); return r;
}
__device__ __forceinline__ float2 unpack2(u64 v) {
    float2 r; asm("mov.b64 {%0, %1}, %2;" : "=f"(r.x), "=f"(r.y) : "l"(v)); return r;
}
__device__ __forceinline__ uint32_t smem_u32(const void* p) {
    return (uint32_t)__cvta_generic_to_shared(p);
}
__device__ __forceinline__ uint32_t to_tf32(float f) {
    uint32_t t; asm("cvt.rna.tf32.f32 %0, %1;" : "=r"(t) : "f"(f)); return t;
}
__device__ __forceinline__ float tf32f(float f) {
    return __uint_as_float(to_tf32(f));
}

#define CP_ASYNC16(dst, src) asm volatile("cp.async.cg.shared.global [%0], [%1], 16;" :: "r"(dst), "l"(src))
#define CP_COMMIT()          asm volatile("cp.async.commit_group;")
#define CP_WAIT1()           asm volatile("cp.async.wait_group 1;")

#define MMA_TF32(C, a0, a1, a2, a3, b0, b1) \
    asm volatile("mma.sync.aligned.m16n8k8.row.col.f32.tf32.tf32.f32 " \
        "{%0,%1,%2,%3}, {%4,%5,%6,%7}, {%8,%9}, {%0,%1,%2,%3};" \
        : "+f"((C)[0]), "+f"((C)[1]), "+f"((C)[2]), "+f"((C)[3]) \
        : "r"(a0), "r"(a1), "r"(a2), "r"(a3), "r"(b0), "r"(b1))

// ---------------- shared 64x64 mma inner (32-k step), fp32 ----------------
__device__ __forceinline__ void mma32(const float (*As)[68], const float (*Bs)[68],
                                      int ty4, int tx4, u64 acc[2][4]) {
#pragma unroll
    for (int kk = 0; kk < 32; kk++) {
        ulonglong2 a2 = *(const ulonglong2*)&As[kk][ty4];
        float4 bv = *(const float4*)&Bs[kk][tx4];
        u64 b0 = pack2(bv.x, bv.x), b1 = pack2(bv.y, bv.y);
        u64 b2 = pack2(bv.z, bv.z), b3 = pack2(bv.w, bv.w);
        acc[0][0] = fma2(a2.x, b0, acc[0][0]); acc[1][0] = fma2(a2.y, b0, acc[1][0]);
        acc[0][1] = fma2(a2.x, b1, acc[0][1]); acc[1][1] = fma2(a2.y, b1, acc[1][1]);
        acc[0][2] = fma2(a2.x, b2, acc[0][2]); acc[1][2] = fma2(a2.y, b2, acc[1][2]);
        acc[0][3] = fma2(a2.x, b3, acc[0][3]); acc[1][3] = fma2(a2.y, b3, acc[1][3]);
    }
}

#define STS8A(buf, v0, v1) { \
    As[buf][lk+0][lrow]=v0.x; As[buf][lk+1][lrow]=v0.y; As[buf][lk+2][lrow]=v0.z; As[buf][lk+3][lrow]=v0.w; \
    As[buf][lk+4][lrow]=v1.x; As[buf][lk+5][lrow]=v1.y; As[buf][lk+6][lrow]=v1.z; As[buf][lk+7][lrow]=v1.w; }
#define STS8B(buf, v0, v1) { \
    Bs[buf][lk+0][lrow]=v0.x; Bs[buf][lk+1][lrow]=v0.y; Bs[buf][lk+2][lrow]=v0.z; Bs[buf][lk+3][lrow]=v0.w; \
    Bs[buf][lk+4][lrow]=v1.x; Bs[buf][lk+5][lrow]=v1.y; Bs[buf][lk+6][lrow]=v1.z; Bs[buf][lk+7][lrow]=v1.w; }

// ---------------- tf32 NT GEMM (512x512x512): qkv (z=0..2) and wf (z=3) ----------------
// CTA tile 64x64, 8 warps as (wm 2) x (wn 4), warp tile 32(M) x 16(N).
// smem: [64 rows][36 floats] per buffer, tf32-preconverted; frag LDS conflict-free.
__global__ __launch_bounds__(256, 2) void gemm_tf32_kernel(
    int zbase,
    const float* __restrict__ query, const float* __restrict__ key, const float* __restrict__ value,
    const float* __restrict__ Wq, const float* __restrict__ bq,
    const float* __restrict__ Wk, const float* __restrict__ bk,
    const float* __restrict__ Wv, const float* __restrict__ bv,
    const float* __restrict__ Wf, const float* __restrict__ bf,
    float* __restrict__ out_final)
{
    int z = zbase + blockIdx.z;
    const float* X; const float* W; const float* bias;
    if (z == 0)      { X = query; W = Wq; bias = bq; }
    else if (z == 1) { X = key;   W = Wk; bias = bk; }
    else if (z == 2) { X = value; W = Wv; bias = bv; }
    else             { X = g_pre; W = Wf; bias = bf; }

    __shared__ __align__(16) float As[2][64][36];
    __shared__ __align__(16) float Bs[2][64][36];

    int tid = threadIdx.x, w = tid >> 5, lane = tid & 31;
    int g = lane >> 2, tg = lane & 3;
    int wm = w & 1, wn = w >> 1;
    int m0 = blockIdx.y * 64, n0 = blockIdx.x * 64;
    int lrow = tid >> 2, lk = (tid & 3) * 8;

    const float* Arow = X + (m0 + lrow) * HH + lk;
    const float* Brow = W + (n0 + lrow) * HH + lk;
    float4 ra0 = *(const float4*)(Arow),  ra1 = *(const float4*)(Arow + 4);
    float4 rb0 = *(const float4*)(Brow),  rb1 = *(const float4*)(Brow + 4);

    float cc[2][2][4];
#pragma unroll
    for (int t = 0; t < 2; t++)
#pragma unroll
        for (int u = 0; u < 2; u++)
#pragma unroll
            for (int j = 0; j < 4; j++) cc[t][u][j] = 0.f;

#pragma unroll 1
    for (int s = 0; s < 16; s++) {
        int buf = s & 1;
        {
            float* ap = &As[buf][lrow][lk];
            ap[0]=tf32f(ra0.x); ap[1]=tf32f(ra0.y); ap[2]=tf32f(ra0.z); ap[3]=tf32f(ra0.w);
            ap[4]=tf32f(ra1.x); ap[5]=tf32f(ra1.y); ap[6]=tf32f(ra1.z); ap[7]=tf32f(ra1.w);
            float* bp = &Bs[buf][lrow][lk];
            bp[0]=tf32f(rb0.x); bp[1]=tf32f(rb0.y); bp[2]=tf32f(rb0.z); bp[3]=tf32f(rb0.w);
            bp[4]=tf32f(rb1.x); bp[5]=tf32f(rb1.y); bp[6]=tf32f(rb1.z); bp[7]=tf32f(rb1.w);
        }
        __syncthreads();
        if (s + 1 < 16) {
            ra0 = *(const float4*)(Arow + (s+1)*32);  ra1 = *(const float4*)(Arow + (s+1)*32 + 4);
            rb0 = *(const float4*)(Brow + (s+1)*32);  rb1 = *(const float4*)(Brow + (s+1)*32 + 4);
        }
#pragma unroll
        for (int kf = 0; kf < 4; kf++) {
            int k8 = kf * 8;
            uint32_t bfr[2][2];
#pragma unroll
            for (int u = 0; u < 2; u++) {
                const float* bp = &Bs[buf][wn*16 + u*8 + g][k8 + tg];
                bfr[u][0] = __float_as_uint(bp[0]);
                bfr[u][1] = __float_as_uint(bp[4]);
            }
#pragma unroll
            for (int t = 0; t < 2; t++) {
                int row = wm*32 + t*16 + g;
                uint32_t a0 = __float_as_uint(As[buf][row    ][k8 + tg]);
                uint32_t a1 = __float_as_uint(As[buf][row + 8][k8 + tg]);
                uint32_t a2 = __float_as_uint(As[buf][row    ][k8 + tg + 4]);
                uint32_t a3 = __float_as_uint(As[buf][row + 8][k8 + tg + 4]);
                MMA_TF32(cc[t][0], a0, a1, a2, a3, bfr[0][0], bfr[0][1]);
                MMA_TF32(cc[t][1], a0, a1, a2, a3, bfr[1][0], bfr[1][1]);
            }
        }
        __syncthreads();
    }

    // epilogue: frag (t,u): rows r0=g, r1=g+8 of subtile; cols c, c+1
#pragma unroll
    for (int t = 0; t < 2; t++) {
#pragma unroll
        for (int u = 0; u < 2; u++) {
            int r0 = m0 + wm*32 + t*16 + g;
            int r1 = r0 + 8;
            int c  = n0 + wn*16 + u*8 + tg*2;
            float bb0 = bias[c], bb1 = bias[c + 1];
            float2 v0 = make_float2(cc[t][u][0] + bb0, cc[t][u][1] + bb1);
            float2 v1 = make_float2(cc[t][u][2] + bb0, cc[t][u][3] + bb1);
            if (z < 3) {
                int n_ = c >> 6, d_ = c & 63;
                int b0_ = r0 >> 8, l0_ = r0 & 255;
                int b1_ = r1 >> 8, l1_ = r1 & 255;
                size_t i0 = ((size_t)(b0_*NHH + n_)*LL + l0_)*DHH + d_;
                size_t i1 = ((size_t)(b1_*NHH + n_)*LL + l1_)*DHH + d_;
                float* dst = (z == 0) ? g_qt : (z == 1) ? g_kt : g_vt;
                *(float2*)&dst[i0] = v0;
                *(float2*)&dst[i1] = v1;
            } else {
                *(float2*)&out_final[(size_t)r0*HH + c] = v0;
                *(float2*)&out_final[(size_t)r1*HH + c] = v1;
            }
        }
    }
}

// ---------------- W2 GEMM (double-buffered fp32): g_w2[b,q,n,h], grid (8,8,8) ----------------
__global__ __launch_bounds__(256, 2) void w2_kernel(const float* __restrict__ Wr,
                                                    const float* __restrict__ v_bias)
{
    int n = blockIdx.z;
    int m0 = blockIdx.y * 64, h0 = blockIdx.x * 64;

    __shared__ __align__(16) float As[2][32][68];
    __shared__ __align__(16) float Bs[2][32][68];

    int tid = threadIdx.x;
    int lrow = tid >> 2, lk = (tid & 3) * 8;
    int brow = tid >> 3, bcol = (tid & 7) * 8;
    int ty4 = (tid >> 4) * 4, tx4 = (tid & 15) * 4;

    int m = m0 + lrow; int b_ = m >> 8, q_ = m & 255;
    const float* Arow = g_qt + ((size_t)(b_*NHH + n)*LL + q_)*DHH + lk;
    const float* Vrow = v_bias + n*DHH + lk;
    const float* Brow = Wr + (size_t)(n*DHH + brow)*HH + h0 + bcol;

    float4 ra0 = *(const float4*)(Arow),  ra1 = *(const float4*)(Arow + 4);
    float4 u0  = *(const float4*)(Vrow),  u1  = *(const float4*)(Vrow + 4);
    ra0.x += u0.x; ra0.y += u0.y; ra0.z += u0.z; ra0.w += u0.w;
    ra1.x += u1.x; ra1.y += u1.y; ra1.z += u1.z; ra1.w += u1.w;
    float4 rb0 = *(const float4*)(Brow),  rb1 = *(const float4*)(Brow + 4);

    u64 acc[2][4];
#pragma unroll
    for (int p = 0; p < 2; p++)
#pragma unroll
        for (int j = 0; j < 4; j++) acc[p][j] = 0ull;

#pragma unroll 1
    for (int s = 0; s < 2; s++) {
        int buf = s & 1;
        STS8A(buf, ra0, ra1);
        *(float4*)&Bs[buf][brow][bcol]     = rb0;
        *(float4*)&Bs[buf][brow][bcol + 4] = rb1;
        __syncthreads();
        if (s == 0) {
            ra0 = *(const float4*)(Arow + 32); ra1 = *(const float4*)(Arow + 36);
            float4 w0 = *(const float4*)(Vrow + 32), w1 = *(const float4*)(Vrow + 36);
            ra0.x += w0.x; ra0.y += w0.y; ra0.z += w0.z; ra0.w += w0.w;
            ra1.x += w1.x; ra1.y += w1.y; ra1.z += w1.z; ra1.w += w1.w;
            rb0 = *(const float4*)(Brow + 32*HH); rb1 = *(const float4*)(Brow + 32*HH + 4);
        }
        mma32(As[buf], Bs[buf], ty4, tx4, acc);
    }

#pragma unroll
    for (int p = 0; p < 2; p++)
#pragma unroll
        for (int j = 0; j < 4; j++) {
            float2 t = unpack2(acc[p][j]);
            int h = h0 + tx4 + j;
            int mm = m0 + ty4 + 2*p;
            int bb_ = mm >> 8, qq_ = mm & 255;
            g_w2[((size_t)(bb_*LL + qq_)*NHH + n)*HH + h] = t.x;
            int mm2 = mm + 1;
            int bb2 = mm2 >> 8, qq2 = mm2 & 255;
            g_w2[((size_t)(bb2*LL + qq2)*NHH + n)*HH + h] = t.y;
        }
}

// ---------------- A_C GEMM (fp32): g_ac[bn,q,k] = (qt+u) @ kt^T, grid (4,4,16) ----------------
__global__ __launch_bounds__(256, 2) void ac_kernel(const float* __restrict__ u_bias)
{
    int bn = blockIdx.z;
    int q0 = blockIdx.y * 64, k0 = blockIdx.x * 64;
    int n = bn & 7;

    __shared__ __align__(16) float As[2][32][68];
    __shared__ __align__(16) float Bs[2][32][68];

    int tid = threadIdx.x;
    int lrow = tid >> 2, lk = (tid & 3) * 8;
    int ty4 = (tid >> 4) * 4, tx4 = (tid & 15) * 4;

    const float* Arow = g_qt + ((size_t)bn*LL + q0 + lrow)*DHH + lk;
    const float* Brow = g_kt + ((size_t)bn*LL + k0 + lrow)*DHH + lk;
    const float* Urow = u_bias + n*DHH + lk;

    float4 ra0 = *(const float4*)(Arow),  ra1 = *(const float4*)(Arow + 4);
    float4 u0  = *(const float4*)(Urow),  u1  = *(const float4*)(Urow + 4);
    ra0.x += u0.x; ra0.y += u0.y; ra0.z += u0.z; ra0.w += u0.w;
    ra1.x += u1.x; ra1.y += u1.y; ra1.z += u1.z; ra1.w += u1.w;
    float4 rb0 = *(const float4*)(Brow),  rb1 = *(const float4*)(Brow + 4);

    u64 acc[2][4];
#pragma unroll
    for (int p = 0; p < 2; p++)
#pragma unroll
        for (int j = 0; j < 4; j++) acc[p][j] = 0ull;

#pragma unroll 1
    for (int s = 0; s < 2; s++) {
        int buf = s & 1;
        STS8A(buf, ra0, ra1); STS8B(buf, rb0, rb1);
        __syncthreads();
        if (s == 0) {
            ra0 = *(const float4*)(Arow + 32); ra1 = *(const float4*)(Arow + 36);
            float4 w0 = *(const float4*)(Urow + 32), w1 = *(const float4*)(Urow + 36);
            ra0.x += w0.x; ra0.y += w0.y; ra0.z += w0.z; ra0.w += w0.w;
            ra1.x += w1.x; ra1.y += w1.y; ra1.z += w1.z; ra1.w += w1.w;
            rb0 = *(const float4*)(Brow + 32); rb1 = *(const float4*)(Brow + 36);
        }
        mma32(As[buf], Bs[buf], ty4, tx4, acc);
    }

#pragma unroll
    for (int p = 0; p < 2; p++) {
        float2 t0 = unpack2(acc[p][0]), t1 = unpack2(acc[p][1]);
        float2 t2 = unpack2(acc[p][2]), t3 = unpack2(acc[p][3]);
        int q = q0 + ty4 + 2*p;
        *(float4*)&g_ac[((size_t)bn*LL + q)  *LL + k0 + tx4] = make_float4(t0.x, t1.x, t2.x, t3.x);
        *(float4*)&g_ac[((size_t)bn*LL + q+1)*LL + k0 + tx4] = make_float4(t0.y, t1.y, t2.y, t3.y);
    }
}

// ---------------- B_D via mma.sync tf32 + softmax, grid (256,2), 256 thr, 2 CTAs/SM ----------------
#define BD_ROW_PITCH 144u                   // 36 floats; bank = (4*row + col) % 32
#define BD_WARP_STRIDE 4608u                // 32 * 144
#define BD_BUF_STRIDE 36864u                // 8 warps * 4608
#define BD_W2_OFF 73728u                    // 2 buffers
#define BD_W2_PITCH 516                     // floats; bank = (4n + h) % 32
#define BD_DYN_TOTAL (73728 + 8*516*4)      // 90240

__global__ __launch_bounds__(256, 2) void bd_kernel(
    const float* __restrict__ rel,
    const int* __restrict__ seq_len, const int* __restrict__ lex_num)
{
    extern __shared__ __align__(16) char dynsm[];
    __shared__ __align__(16) float ss[NHH * 260];

    int q = blockIdx.x, b = blockIdx.y;
    int tid = threadIdx.x, w = tid >> 5, lane = tid & 31;
    int g = lane >> 2, tg = lane & 3;

    float* w2s = (float*)(dynsm + BD_W2_OFF);
    {
        const float* w2p = g_w2 + (size_t)(b*LL + q)*NHH*HH;
#pragma unroll
        for (int p = 0; p < 16; p++) {
            int i = tid + p*256;
            int n_ = i >> 9, h_ = i & 511;
            w2s[n_*BD_W2_PITCH + h_] = __uint_as_float(to_tf32(w2p[i]));
        }
    }

    const float* relq = rel + ((size_t)(b*LL + q)*LL + w*32)*HH;
    uint32_t mybuf = smem_u32(dynsm) + w*BD_WARP_STRIDE;

#define BD_LOAD(c) { \
    uint32_t dst_ = mybuf + ((uint32_t)((c) & 1))*BD_BUF_STRIDE; \
    const float* src_ = relq + (c)*32; \
    _Pragma("unroll") \
    for (int p_ = 0; p_ < 8; p_++) { \
        int li_ = p_*32 + lane; int rr_ = li_ >> 3, j_ = li_ & 7; \
        CP_ASYNC16(dst_ + rr_*BD_ROW_PITCH + j_*16u, src_ + (size_t)rr_*HH + j_*4); \
    } \
    CP_COMMIT(); }

    BD_LOAD(0); BD_LOAD(1);
    __syncthreads();   // w2s visible to all warps

    float cc[2][4];
#pragma unroll
    for (int t = 0; t < 2; t++)
#pragma unroll
        for (int j = 0; j < 4; j++) cc[t][j] = 0.f;

#pragma unroll 1
    for (int i = 0; i < 16; i++) {
        CP_WAIT1();                          // chunk i landed (i+1 may be pending)

        const float* bufp = (const float*)(dynsm + (size_t)(i & 1)*BD_BUF_STRIDE
                                                 + (size_t)w*BD_WARP_STRIDE);
        uint32_t areg[2][4][4];
        uint32_t breg[4][2];
#pragma unroll
        for (int s = 0; s < 4; s++) {
            int hg = i*32 + s*8;
            breg[s][0] = __float_as_uint(w2s[g*BD_W2_PITCH + hg + tg]);
            breg[s][1] = __float_as_uint(w2s[g*BD_W2_PITCH + hg + tg + 4]);
#pragma unroll
            for (int t = 0; t < 2; t++) {
                const float* ap = bufp + (t*16 + g)*36 + s*8 + tg;
                areg[t][s][0] = to_tf32(ap[0]);
                areg[t][s][1] = to_tf32(ap[8*36]);
                areg[t][s][2] = to_tf32(ap[4]);
                areg[t][s][3] = to_tf32(ap[8*36 + 4]);
            }
        }

        if (i + 2 < 16) { BD_LOAD(i + 2); } else { CP_COMMIT(); }

#pragma unroll
        for (int s = 0; s < 4; s++)
#pragma unroll
            for (int t = 0; t < 2; t++) {
                MMA_TF32(cc[t], areg[t][s][0], areg[t][s][1], areg[t][s][2], areg[t][s][3],
                         breg[s][0], breg[s][1]);
            }
    }

    // scatter C frags to ss[n][k]
#pragma unroll
    for (int t = 0; t < 2; t++) {
        int k = w*32 + t*16 + g;
        int n0 = tg*2;
        ss[n0*260 + k]           = cc[t][0];
        ss[(n0 + 1)*260 + k]     = cc[t][1];
        ss[n0*260 + k + 8]       = cc[t][2];
        ss[(n0 + 1)*260 + k + 8] = cc[t][3];
    }
    __syncthreads();

    // softmax head w: ac (from gmem) + bd (from ss), mask, normalize
    int total = seq_len[b] + lex_num[b];
    {
        const float* acp = g_ac + ((size_t)(b*NHH + w)*LL + q)*LL + lane*8;
        float4 a0 = *(const float4*)(acp);
        float4 a1 = *(const float4*)(acp + 4);
        float v[8];
        v[0]=a0.x; v[1]=a0.y; v[2]=a0.z; v[3]=a0.w;
        v[4]=a1.x; v[5]=a1.y; v[6]=a1.z; v[7]=a1.w;
#pragma unroll
        for (int t = 0; t < 8; t++) {
            int kidx = lane*8 + t;
            float s = v[t] + ss[w*260 + kidx];
            v[t] = (kidx < total) ? s * 0.125f : -1e15f;
        }
        float mx = v[0];
#pragma unroll
        for (int t = 1; t < 8; t++) mx = fmaxf(mx, v[t]);
#pragma unroll
        for (int sft = 16; sft > 0; sft >>= 1) mx = fmaxf(mx, __shfl_xor_sync(0xffffffffu, mx, sft));
        float sum = 0.f;
#pragma unroll
        for (int t = 0; t < 8; t++) { v[t] = expf(v[t] - mx); sum += v[t]; }
#pragma unroll
        for (int sft = 16; sft > 0; sft >>= 1) sum += __shfl_xor_sync(0xffffffffu, sum, sft);
        float inv = 1.0f / sum;
#pragma unroll
        for (int t = 0; t < 8; t++) v[t] *= inv;
        float* op = g_attn + ((size_t)(b*NHH + w)*LL + q)*LL + lane*8;
        *(float4*)(op)     = make_float4(v[0], v[1], v[2], v[3]);
        *(float4*)(op + 4) = make_float4(v[4], v[5], v[6], v[7]);
    }
}

// ---------------- AV GEMM (NN fp32): g_pre = attn @ v, grid (4,16) ----------------
__global__ __launch_bounds__(256, 2) void av_kernel()
{
    int q0 = blockIdx.x * 64, bn = blockIdx.y;
    int b = bn >> 3, n = bn & 7;

    __shared__ __align__(16) float As[2][32][68];
    __shared__ __align__(16) float Bs[2][32][68];

    int tid = threadIdx.x;
    int lrow = tid >> 2, lk = (tid & 3) * 8;
    int brow = tid >> 3, bcol = (tid & 7) * 8;
    int ty4 = (tid >> 4) * 4, tx4 = (tid & 15) * 4;

    const float* Arow = g_attn + ((size_t)bn*LL + q0 + lrow)*LL + lk;
    const float* Brow = g_vt   + (size_t)bn*LL*DHH + brow*DHH + bcol;

    float4 ra0 = *(const float4*)(Arow),  ra1 = *(const float4*)(Arow + 4);
    float4 rb0 = *(const float4*)(Brow),  rb1 = *(const float4*)(Brow + 4);

    u64 acc[2][4];
#pragma unroll
    for (int p = 0; p < 2; p++)
#pragma unroll
        for (int j = 0; j < 4; j++) acc[p][j] = 0ull;

#pragma unroll 1
    for (int s = 0; s < 8; s++) {
        int buf = s & 1;
        STS8A(buf, ra0, ra1);
        *(float4*)&Bs[buf][brow][bcol]     = rb0;
        *(float4*)&Bs[buf][brow][bcol + 4] = rb1;
        __syncthreads();
        if (s + 1 < 8) {
            ra0 = *(const float4*)(Arow + (s+1)*32);            ra1 = *(const float4*)(Arow + (s+1)*32 + 4);
            rb0 = *(const float4*)(Brow + (s+1)*32*DHH);        rb1 = *(const float4*)(Brow + (s+1)*32*DHH + 4);
        }
        mma32(As[buf], Bs[buf], ty4, tx4, acc);
    }

#pragma unroll
    for (int p = 0; p < 2; p++)
#pragma unroll
        for (int j = 0; j < 4; j++) {
            float2 t = unpack2(acc[p][j]);
            int d = tx4 + j;
            int q = q0 + ty4 + 2*p;
            g_pre[((size_t)(b*LL + q))    *HH + n*DHH + d] = t.x;
            g_pre[((size_t)(b*LL + q + 1))*HH + n*DHH + d] = t.y;
        }
}

// ---------------- launch ----------------
extern "C" void kernel_launch(void* const* d_in, const int* in_sizes, int n_in,
                              void* d_out, int out_size) {
    (void)in_sizes; (void)n_in; (void)out_size;
    const float* key     = (const float*)d_in[0];
    const float* query   = (const float*)d_in[1];
    const float* value   = (const float*)d_in[2];
    const float* rel     = (const float*)d_in[3];
    const float* Wk      = (const float*)d_in[4];
    const float* bk      = (const float*)d_in[5];
    const float* Wq      = (const float*)d_in[6];
    const float* bq      = (const float*)d_in[7];
    const float* Wv      = (const float*)d_in[8];
    const float* bv      = (const float*)d_in[9];
    const float* Wr      = (const float*)d_in[10];
    // d_in[11] = br: constant per score row -> cancels in softmax
    const float* u_bias  = (const float*)d_in[12];
    const float* v_bias  = (const float*)d_in[13];
    const float* Wf      = (const float*)d_in[14];
    const float* bf      = (const float*)d_in[15];
    const int*   seq_len = (const int*)d_in[16];
    const int*   lex_num = (const int*)d_in[17];
    float* out = (float*)d_out;

    static int bd_smem_set = 0;
    if (!bd_smem_set) {
        cudaFuncSetAttribute(bd_kernel, cudaFuncAttributeMaxDynamicSharedMemorySize, BD_DYN_TOTAL);
        bd_smem_set = 1;
    }

    gemm_tf32_kernel<<<dim3(8, 8, 3), 256>>>(0, query, key, value, Wq, bq, Wk, bk, Wv, bv, Wf, bf, out);
    w2_kernel<<<dim3(8, 8, NHH), 256>>>(Wr, v_bias);
    ac_kernel<<<dim3(4, 4, 16), 256>>>(u_bias);
    bd_kernel<<<dim3(LL, BB), 256, BD_DYN_TOTAL>>>(rel, seq_len, lex_num);
    av_kernel<<<dim3(4, 16), 256>>>();
    gemm_tf32_kernel<<<dim3(8, 8, 1), 256>>>(3, query, key, value, Wq, bq, Wk, bk, Wv, bv, Wf, bf, out);
}